// round 6
// baseline (speedup 1.0000x reference)
#include <cuda_runtime.h>
#include <math.h>

// Problem constants (fixed by the reference)
#define NN 20000          // nodes
#define EE 160000         // edges
#define DD 1000           // feature dim
#define TD 3000           // 3*D
#define NLAYERS 3
#define D4 250            // D/4 (float4 count per row)

#define DIVUP(a,b) (((a)+(b)-1)/(b))

// -------- scratch (device globals: the sanctioned no-alloc workaround) --------
__device__ float g_m  [(size_t)NN * DD];   // 80 MB
__device__ float g_agg[(size_t)NN * DD];   // 80 MB
__device__ float g_gi [(size_t)NN * TD];   // 240 MB
__device__ float g_gh [(size_t)NN * TD];   // 240 MB
__device__ float g_h  [(size_t)NN * DD];   // 80 MB

// ============================================================================
// SGEMM: C[M,Nn] = A[M,K] @ B  (+ bias[col] if BIAS)
//   BT=false: B stored row-major [K, Nn]
//   BT=true : B stored [Nn, K] (i.e., C = A @ B^T), K-contiguous per output col
// Tiles: 128x128x8, 256 threads, 8x8 per-thread microtile.
// Double-buffered smem staging: global->reg prefetch overlaps FFMA block,
// one __syncthreads per K-step.
// Requires: K % 8 == 0, Nn % 4 == 0 (holds: K=1000, Nn in {1000,3000}).
// ============================================================================
template<bool BT, bool BIAS>
__global__ __launch_bounds__(256)
void sgemm_k(const float* __restrict__ A, const float* __restrict__ B,
             const float* __restrict__ bias, float* __restrict__ C,
             int M, int Nn, int K)
{
    __shared__ float As[2][8][132];
    __shared__ float Bs[2][8][132];

    const int tid = threadIdx.x;
    const int tx = tid & 15;        // 0..15 -> 8 cols each
    const int ty = tid >> 4;        // 0..15 -> 8 rows each
    const int row0 = blockIdx.y * 128;
    const int col0 = blockIdx.x * 128;

    float acc[8][8];
#pragma unroll
    for (int i = 0; i < 8; i++)
#pragma unroll
        for (int j = 0; j < 8; j++) acc[i][j] = 0.f;

    // A tile load mapping: one float4 along K per thread
    const int a_m = tid >> 1;             // 0..127
    const int a_k = (tid & 1) * 4;        // 0 or 4
    const bool a_valid = (row0 + a_m) < M;
    const float* Aptr = A + (size_t)(row0 + a_m) * K + a_k;

    // B tile load mapping
    int b_k, b_n;
    const float* Bptr;
    bool b_valid;
    if (BT) {
        b_n = tid >> 1;                   // 0..127
        b_k = (tid & 1) * 4;
        b_valid = (col0 + b_n) < Nn;
        Bptr = B + (size_t)(col0 + b_n) * K + b_k;
    } else {
        b_k = tid >> 5;                   // 0..7
        b_n = (tid & 31) * 4;             // 0..124
        b_valid = (col0 + b_n + 3) < Nn;  // Nn%4==0 -> all-or-nothing
        Bptr = B + (size_t)b_k * Nn + (col0 + b_n);
    }

    const float4 zero4 = make_float4(0.f, 0.f, 0.f, 0.f);

    // ---- preload tile kt=0 into buffer 0 ----
    {
        float4 av = a_valid ? *(const float4*)(Aptr) : zero4;
        As[0][a_k + 0][a_m] = av.x;
        As[0][a_k + 1][a_m] = av.y;
        As[0][a_k + 2][a_m] = av.z;
        As[0][a_k + 3][a_m] = av.w;
        if (BT) {
            float4 bv = b_valid ? *(const float4*)(Bptr) : zero4;
            Bs[0][b_k + 0][b_n] = bv.x;
            Bs[0][b_k + 1][b_n] = bv.y;
            Bs[0][b_k + 2][b_n] = bv.z;
            Bs[0][b_k + 3][b_n] = bv.w;
        } else {
            float4 bv = b_valid ? *(const float4*)(Bptr) : zero4;
            *(float4*)&Bs[0][b_k][b_n] = bv;
        }
    }
    __syncthreads();

    int buf = 0;
    for (int kt = 0; kt < K; kt += 8) {
        // ---- prefetch next tile into registers (overlaps compute) ----
        const bool has_next = (kt + 8) < K;
        float4 av2 = zero4, bv2 = zero4;
        if (has_next) {
            if (a_valid) av2 = *(const float4*)(Aptr + kt + 8);
            if (BT) {
                if (b_valid) bv2 = *(const float4*)(Bptr + kt + 8);
            } else {
                if (b_valid) bv2 = *(const float4*)(Bptr + (size_t)(kt + 8) * Nn);
            }
        }

        // ---- compute on current buffer ----
#pragma unroll
        for (int k = 0; k < 8; k++) {
            float a[8], b[8];
            float4 t;
            t = *(const float4*)&As[buf][k][ty * 8];     a[0]=t.x; a[1]=t.y; a[2]=t.z; a[3]=t.w;
            t = *(const float4*)&As[buf][k][ty * 8 + 4]; a[4]=t.x; a[5]=t.y; a[6]=t.z; a[7]=t.w;
            t = *(const float4*)&Bs[buf][k][tx * 8];     b[0]=t.x; b[1]=t.y; b[2]=t.z; b[3]=t.w;
            t = *(const float4*)&Bs[buf][k][tx * 8 + 4]; b[4]=t.x; b[5]=t.y; b[6]=t.z; b[7]=t.w;
#pragma unroll
            for (int i = 0; i < 8; i++)
#pragma unroll
                for (int j = 0; j < 8; j++)
                    acc[i][j] += a[i] * b[j];
        }

        // ---- stage prefetched tile into the other buffer ----
        if (has_next) {
            int nb = buf ^ 1;
            As[nb][a_k + 0][a_m] = av2.x;
            As[nb][a_k + 1][a_m] = av2.y;
            As[nb][a_k + 2][a_m] = av2.z;
            As[nb][a_k + 3][a_m] = av2.w;
            if (BT) {
                Bs[nb][b_k + 0][b_n] = bv2.x;
                Bs[nb][b_k + 1][b_n] = bv2.y;
                Bs[nb][b_k + 2][b_n] = bv2.z;
                Bs[nb][b_k + 3][b_n] = bv2.w;
            } else {
                *(float4*)&Bs[nb][b_k][b_n] = bv2;
            }
            __syncthreads();
        }
        buf ^= 1;
    }

    // Epilogue (Nn%4==0, per-float4 all-or-nothing guards)
#pragma unroll
    for (int i = 0; i < 8; i++) {
        int r = row0 + ty * 8 + i;
        if (r >= M) continue;
#pragma unroll
        for (int j = 0; j < 8; j += 4) {
            int c = col0 + tx * 8 + j;
            if (c + 3 < Nn) {
                float4 v = make_float4(acc[i][j], acc[i][j+1], acc[i][j+2], acc[i][j+3]);
                if (BIAS) {
                    v.x += bias[c];
                    v.y += bias[c + 1];
                    v.z += bias[c + 2];
                    v.w += bias[c + 3];
                }
                *(float4*)&C[(size_t)r * Nn + c] = v;
            }
        }
    }
}

// ============================================================================
// zero: float4 clear
// ============================================================================
__global__ void zero_k(float4* __restrict__ p, int n4)
{
    int i = blockIdx.x * blockDim.x + threadIdx.x;
    if (i < n4) p[i] = make_float4(0.f, 0.f, 0.f, 0.f);
}

// ============================================================================
// scatter: one block per edge; agg[dst[e]] += m[src[e]] * ew[e]
// 4 scalar atomicAdd per thread (result unused -> RED.E.ADD.F32)
// ============================================================================
__global__ __launch_bounds__(256)
void scatter_k(const float* __restrict__ m, const int* __restrict__ src,
               const int* __restrict__ dst, const float* __restrict__ ew,
               float* __restrict__ agg)
{
    int e = blockIdx.x;
    int t = threadIdx.x;
    if (t >= D4) return;
    int s = src[e];
    int d = dst[e];
    float w = ew[e];
    float4 v = *(const float4*)(m + (size_t)s * DD + t * 4);
    float* a = agg + (size_t)d * DD + t * 4;
    atomicAdd(a + 0, v.x * w);
    atomicAdd(a + 1, v.y * w);
    atomicAdd(a + 2, v.z * w);
    atomicAdd(a + 3, v.w * w);
}

// ============================================================================
// GRU elementwise (gate order r, z, n):
//   r = sig(i_r + h_r); z = sig(i_z + h_z); n = tanh(i_n + r*h_n)
//   h' = (1-z)*n + z*h
// gi/gh already contain biases from GEMM epilogue.
// ============================================================================
__device__ __forceinline__ float gru1(float ir, float iz, float inn,
                                      float hr, float hz, float hn, float h)
{
    float r = 1.f / (1.f + expf(-(ir + hr)));
    float z = 1.f / (1.f + expf(-(iz + hz)));
    float n = tanhf(inn + r * hn);
    return (1.f - z) * n + z * h;
}

__global__ __launch_bounds__(256)
void gru_k(const float4* __restrict__ gi, const float4* __restrict__ gh,
           const float4* __restrict__ hin, float4* __restrict__ hout)
{
    int idx = blockIdx.x * blockDim.x + threadIdx.x;   // over NN * D4
    if (idx >= NN * D4) return;
    int n  = idx / D4;
    int dv = idx - n * D4;
    size_t b3 = (size_t)n * (3 * D4);
    float4 ir = gi[b3 + dv];
    float4 iz = gi[b3 + D4 + dv];
    float4 in_ = gi[b3 + 2 * D4 + dv];
    float4 hr = gh[b3 + dv];
    float4 hz = gh[b3 + D4 + dv];
    float4 hn = gh[b3 + 2 * D4 + dv];
    float4 h = hin[(size_t)n * D4 + dv];
    float4 o;
    o.x = gru1(ir.x, iz.x, in_.x, hr.x, hz.x, hn.x, h.x);
    o.y = gru1(ir.y, iz.y, in_.y, hr.y, hz.y, hn.y, h.y);
    o.z = gru1(ir.z, iz.z, in_.z, hr.z, hz.z, hn.z, h.z);
    o.w = gru1(ir.w, iz.w, in_.w, hr.w, hz.w, hn.w, h.w);
    hout[(size_t)n * D4 + dv] = o;
}

// ============================================================================
// Final: out[n] = sum_d relu(h[n,d]) * fc_w[d] + fc_b   (warp per node)
// ============================================================================
__global__ __launch_bounds__(256)
void fc_k(const float* __restrict__ h, const float* __restrict__ fw,
          const float* __restrict__ fb, float* __restrict__ out)
{
    int warp = (blockIdx.x * 256 + threadIdx.x) >> 5;
    int lane = threadIdx.x & 31;
    if (warp >= NN) return;
    const float4* h4 = (const float4*)(h + (size_t)warp * DD);
    const float4* w4 = (const float4*)fw;
    float s = 0.f;
    for (int i = lane; i < D4; i += 32) {
        float4 hv = h4[i];
        float4 wv = w4[i];
        s += fmaxf(hv.x, 0.f) * wv.x + fmaxf(hv.y, 0.f) * wv.y +
             fmaxf(hv.z, 0.f) * wv.z + fmaxf(hv.w, 0.f) * wv.w;
    }
#pragma unroll
    for (int off = 16; off; off >>= 1)
        s += __shfl_down_sync(0xffffffffu, s, off);
    if (lane == 0) out[warp] = s + fb[0];
}

// ============================================================================
// launch
// ============================================================================
extern "C" void kernel_launch(void* const* d_in, const int* in_sizes, int n_in,
                              void* d_out, int out_size)
{
    const float* x      = (const float*)d_in[0];
    const int*   ei     = (const int*)  d_in[1];
    const float* ew     = (const float*)d_in[2];
    const float* weight = (const float*)d_in[3];
    const float* w_ih   = (const float*)d_in[4];
    const float* w_hh   = (const float*)d_in[5];
    const float* b_ih   = (const float*)d_in[6];
    const float* b_hh   = (const float*)d_in[7];
    const float* fc_w   = (const float*)d_in[8];
    const float* fc_b   = (const float*)d_in[9];
    float* out = (float*)d_out;

    float *pm, *pagg, *pgi, *pgh, *ph;
    cudaGetSymbolAddress((void**)&pm,   g_m);
    cudaGetSymbolAddress((void**)&pagg, g_agg);
    cudaGetSymbolAddress((void**)&pgi,  g_gi);
    cudaGetSymbolAddress((void**)&pgh,  g_gh);
    cudaGetSymbolAddress((void**)&ph,   g_h);

    const int* src = ei;
    const int* dst = ei + EE;

    dim3 grid1(DIVUP(DD, 128), DIVUP(NN, 128));   // m GEMM: 8 x 157
    dim3 grid3(DIVUP(TD, 128), DIVUP(NN, 128));   // gate GEMMs: 24 x 157
    int ew_blocks = DIVUP(NN * D4, 256);

    for (int l = 0; l < NLAYERS; l++) {
        const float* hin = (l == 0) ? x : ph;

        // m = h @ W[l]
        sgemm_k<false, false><<<grid1, 256>>>(hin, weight + (size_t)l * DD * DD,
                                              nullptr, pm, NN, DD, DD);
        // agg = scatter_add(m[src] * ew, dst)
        zero_k<<<ew_blocks, 256>>>((float4*)pagg, NN * D4);
        scatter_k<<<EE, 256>>>(pm, src, dst, ew, pagg);

        // gi = agg @ w_ih^T + b_ih ; gh = h @ w_hh^T + b_hh
        sgemm_k<true, true><<<grid3, 256>>>(pagg, w_ih, b_ih, pgi, NN, TD, DD);
        sgemm_k<true, true><<<grid3, 256>>>(hin,  w_hh, b_hh, pgh, NN, TD, DD);

        // h = GRU(gi, gh, h)
        gru_k<<<ew_blocks, 256>>>((const float4*)pgi, (const float4*)pgh,
                                  (const float4*)hin, (float4*)ph);
    }

    // out = relu(h) @ fc_w^T + fc_b
    fc_k<<<DIVUP(NN, 8), 256>>>(ph, fc_w, fc_b, out);
}

// round 11
// speedup vs baseline: 2.3444x; 2.3444x over previous
#include <cuda_runtime.h>
#include <cuda_bf16.h>
#include <math.h>
#include <stdint.h>

// Problem constants (fixed by the reference)
#define NN 20000          // nodes
#define EE 160000         // edges
#define DD 1000           // feature dim
#define TD 3000           // 3*D
#define NLAYERS 3
#define D4 250            // D/4
#define KP 1024           // K padded to multiple of 64
#define KP8 (KP/8)        // uint4 (8 bf16) per padded row = 128
#define NCHUNK (KP/64)    // 16

#define DIVUP(a,b) (((a)+(b)-1)/(b))

// ---------------- scratch (device globals: sanctioned no-alloc path) --------
__device__ float g_m  [(size_t)NN * DD];   // 80 MB
__device__ float g_agg[(size_t)NN * DD];   // 80 MB
__device__ float g_gi [(size_t)NN * TD];   // 240 MB
__device__ float g_gh [(size_t)NN * TD];   // 240 MB
__device__ float g_h  [(size_t)NN * DD];   // 80 MB
// bf16 hi/lo split operand buffers (K padded to KP, tail zeros)
__device__ __nv_bfloat16 g_a_hi [(size_t)NN * KP];
__device__ __nv_bfloat16 g_a_lo [(size_t)NN * KP];
__device__ __nv_bfloat16 g_h_hi [(size_t)NN * KP];
__device__ __nv_bfloat16 g_h_lo [(size_t)NN * KP];
__device__ __nv_bfloat16 g_wih_hi[(size_t)TD * KP];
__device__ __nv_bfloat16 g_wih_lo[(size_t)TD * KP];
__device__ __nv_bfloat16 g_whh_hi[(size_t)TD * KP];
__device__ __nv_bfloat16 g_whh_lo[(size_t)TD * KP];
__device__ __nv_bfloat16 g_wt_hi [(size_t)NLAYERS * DD * KP];
__device__ __nv_bfloat16 g_wt_lo [(size_t)NLAYERS * DD * KP];

// ====================== helpers (sm_80-baseline PTX only) ===================
__device__ __forceinline__ uint32_t smem_u32(const void* p) {
    uint32_t a;
    asm("{ .reg .u64 t; cvta.to.shared.u64 t, %1; cvt.u32.u64 %0, t; }"
        : "=r"(a) : "l"(p));
    return a;
}
__device__ __forceinline__ void cp16(uint32_t s, const void* g, uint32_t sz) {
    asm volatile("cp.async.cg.shared.global [%0], [%1], 16, %2;"
                 :: "r"(s), "l"(g), "r"(sz) : "memory");
}
#define CP_COMMIT() asm volatile("cp.async.commit_group;" ::: "memory")
#define CP_WAIT1()  asm volatile("cp.async.wait_group 1;" ::: "memory")
#define CP_WAIT0()  asm volatile("cp.async.wait_group 0;" ::: "memory")

// D += A(16x16 bf16, row) @ B(16x8 bf16, col)
__device__ __forceinline__ void mma16816(float* d, const uint32_t* a, const uint32_t* b) {
    asm volatile(
        "mma.sync.aligned.m16n8k16.row.col.f32.bf16.bf16.f32 "
        "{%0,%1,%2,%3}, {%4,%5,%6,%7}, {%8,%9}, {%0,%1,%2,%3};"
        : "+f"(d[0]), "+f"(d[1]), "+f"(d[2]), "+f"(d[3])
        : "r"(a[0]), "r"(a[1]), "r"(a[2]), "r"(a[3]), "r"(b[0]), "r"(b[1]));
}

// ============================================================================
// fp32 -> bf16 hi/lo split, row-major [M][Kin] -> [M][KP] (tail zero)
// ============================================================================
__global__ __launch_bounds__(256)
void conv_split_k(const float* __restrict__ in, __nv_bfloat16* __restrict__ hi,
                  __nv_bfloat16* __restrict__ lo, int M, int Kin)
{
    int idx = blockIdx.x * blockDim.x + threadIdx.x;   // over M * KP/4
    if (idx >= M * (KP / 4)) return;
    int r  = idx / (KP / 4);
    int c  = (idx - r * (KP / 4)) * 4;
    float4 v = make_float4(0.f, 0.f, 0.f, 0.f);
    if (c + 3 < Kin) v = *(const float4*)(in + (size_t)r * Kin + c);
    __nv_bfloat16 h0 = __float2bfloat16(v.x), h1 = __float2bfloat16(v.y);
    __nv_bfloat16 h2 = __float2bfloat16(v.z), h3 = __float2bfloat16(v.w);
    __nv_bfloat16 l0 = __float2bfloat16(v.x - __bfloat162float(h0));
    __nv_bfloat16 l1 = __float2bfloat16(v.y - __bfloat162float(h1));
    __nv_bfloat16 l2 = __float2bfloat16(v.z - __bfloat162float(h2));
    __nv_bfloat16 l3 = __float2bfloat16(v.w - __bfloat162float(h3));
    uint2 ph, pl;
    ph.x = ((uint32_t)__bfloat16_as_ushort(h1) << 16) | __bfloat16_as_ushort(h0);
    ph.y = ((uint32_t)__bfloat16_as_ushort(h3) << 16) | __bfloat16_as_ushort(h2);
    pl.x = ((uint32_t)__bfloat16_as_ushort(l1) << 16) | __bfloat16_as_ushort(l0);
    pl.y = ((uint32_t)__bfloat16_as_ushort(l3) << 16) | __bfloat16_as_ushort(l2);
    *(uint2*)(hi + (size_t)r * KP + c) = ph;
    *(uint2*)(lo + (size_t)r * KP + c) = pl;
}

// ============================================================================
// weight[l] is [K=1000][N=1000] (N contiguous); emit transposed split
// ============================================================================
__global__ __launch_bounds__(256)
void convT_split_k(const float* __restrict__ w, __nv_bfloat16* __restrict__ hi,
                   __nv_bfloat16* __restrict__ lo)
{
    int idx = blockIdx.x * blockDim.x + threadIdx.x;   // over DD * KP/4
    if (idx >= DD * (KP / 4)) return;
    int n = idx / (KP / 4);
    int k = (idx - n * (KP / 4)) * 4;
    float4 v = make_float4(0.f, 0.f, 0.f, 0.f);
    if (k + 3 < DD) {
        v.x = w[(size_t)(k    ) * DD + n];
        v.y = w[(size_t)(k + 1) * DD + n];
        v.z = w[(size_t)(k + 2) * DD + n];
        v.w = w[(size_t)(k + 3) * DD + n];
    }
    __nv_bfloat16 h0 = __float2bfloat16(v.x), h1 = __float2bfloat16(v.y);
    __nv_bfloat16 h2 = __float2bfloat16(v.z), h3 = __float2bfloat16(v.w);
    __nv_bfloat16 l0 = __float2bfloat16(v.x - __bfloat162float(h0));
    __nv_bfloat16 l1 = __float2bfloat16(v.y - __bfloat162float(h1));
    __nv_bfloat16 l2 = __float2bfloat16(v.z - __bfloat162float(h2));
    __nv_bfloat16 l3 = __float2bfloat16(v.w - __bfloat162float(h3));
    uint2 ph, pl;
    ph.x = ((uint32_t)__bfloat16_as_ushort(h1) << 16) | __bfloat16_as_ushort(h0);
    ph.y = ((uint32_t)__bfloat16_as_ushort(h3) << 16) | __bfloat16_as_ushort(h2);
    pl.x = ((uint32_t)__bfloat16_as_ushort(l1) << 16) | __bfloat16_as_ushort(l0);
    pl.y = ((uint32_t)__bfloat16_as_ushort(l3) << 16) | __bfloat16_as_ushort(l2);
    *(uint2*)(hi + (size_t)n * KP + k) = ph;
    *(uint2*)(lo + (size_t)n * KP + k) = pl;
}

// ============================================================================
// mma.sync GEMM: C[M,Nn] = Ahi@Bhi^T + Ahi@Blo^T + Alo@Bhi^T (+ bias)
// A: [M][KP] bf16 K-major; B: [Nn][KP] bf16 K-major. fp32 register accum.
// CTA tile 128x128, K chunk 64, 2-stage cp.async pipeline.
// 256 threads = 8 warps, warp tile 64x32 (4 m-atoms x 4 n-atoms of 16x8).
// SMEM row stride 144 B (72 bf16): frag reads are bank-conflict-free.
// ============================================================================
#define ASTRIDE 144
#define TILE_SB (128 * ASTRIDE)   // 18432 B per 128x64 bf16 tile
#define STAGE_SB (4 * TILE_SB)    // Ahi, Alo, Bhi, Blo = 73728 B
#define SMEM_DYN (2 * STAGE_SB)   // 147456 B

template<bool BIAS>
__global__ __launch_bounds__(256, 1)
void mma_gemm_k(const __nv_bfloat16* __restrict__ Ahi, const __nv_bfloat16* __restrict__ Alo,
                const __nv_bfloat16* __restrict__ Bhi, const __nv_bfloat16* __restrict__ Blo,
                const float* __restrict__ bias, float* __restrict__ C,
                int M, int Nn)
{
    extern __shared__ char smem[];
    const int tid  = threadIdx.x;
    const int lane = tid & 31;
    const int wid  = tid >> 5;
    const int gr   = lane >> 2;     // 0..7
    const int gc   = lane & 3;      // 0..3
    const int wm   = wid >> 2;      // 0..1  (64-row half)
    const int wn   = wid & 3;       // 0..3  (32-col quarter)
    const int row0 = blockIdx.y * 128;
    const int col0 = blockIdx.x * 128;

    const uint4* pAhi = (const uint4*)Ahi;
    const uint4* pAlo = (const uint4*)Alo;
    const uint4* pBhi = (const uint4*)Bhi;
    const uint4* pBlo = (const uint4*)Blo;

    const uint32_t sbase = smem_u32(smem);

    float acc[4][4][4];
#pragma unroll
    for (int i = 0; i < 4; i++)
#pragma unroll
        for (int j = 0; j < 4; j++)
#pragma unroll
            for (int k = 0; k < 4; k++) acc[i][j][k] = 0.f;

    // per-thread load slots: q = tid, tid+256, tid+512, tid+768
    // row = q>>3 (0..127), u = q&7 (uint4 within 64-bf16 row)
    const int lrow = tid >> 3;          // base row for q = tid
    const int lu   = tid & 7;

    // ---- chunk loader: stage in {0,1} ----
    auto load_chunk = [&](int c, int stage) {
        const uint32_t st = sbase + stage * STAGE_SB;
        const int k0u = c * 8;
#pragma unroll
        for (int it = 0; it < 4; ++it) {
            const int rr = lrow + it * 32;
            const uint32_t soff = (uint32_t)(rr * ASTRIDE + lu * 16);
            const int ar = row0 + rr;
            const uint32_t asz = (ar < M) ? 16u : 0u;
            const size_t ga = (size_t)((ar < M) ? ar : 0) * KP8 + (k0u + lu);
            cp16(st + 0 * TILE_SB + soff, pAhi + ga, asz);
            cp16(st + 1 * TILE_SB + soff, pAlo + ga, asz);
            const int br = col0 + rr;
            const uint32_t bsz = (br < Nn) ? 16u : 0u;
            const size_t gb = (size_t)((br < Nn) ? br : 0) * KP8 + (k0u + lu);
            cp16(st + 2 * TILE_SB + soff, pBhi + gb, bsz);
            cp16(st + 3 * TILE_SB + soff, pBlo + gb, bsz);
        }
        CP_COMMIT();
    };

    load_chunk(0, 0);

    for (int c = 0; c < NCHUNK; ++c) {
        if (c + 1 < NCHUNK) {
            load_chunk(c + 1, (c + 1) & 1);
            CP_WAIT1();
        } else {
            CP_WAIT0();
        }
        __syncthreads();

        const char* st = smem + (c & 1) * STAGE_SB;
        const char* sAh = st;
        const char* sAl = st + TILE_SB;
        const char* sBh = st + 2 * TILE_SB;
        const char* sBl = st + 3 * TILE_SB;

#pragma unroll
        for (int ks = 0; ks < 4; ++ks) {
            const int k0 = ks * 16;
            const int kb = k0 * 2 + gc * 4;      // byte offset of this thread's k-pair

            uint32_t a[2][4][4];
#pragma unroll
            for (int mt = 0; mt < 4; ++mt) {
                const int r = wm * 64 + mt * 16 + gr;
                const int o = r * ASTRIDE + kb;
                a[0][mt][0] = *(const uint32_t*)(sAh + o);
                a[0][mt][1] = *(const uint32_t*)(sAh + o + 8 * ASTRIDE);
                a[0][mt][2] = *(const uint32_t*)(sAh + o + 16);
                a[0][mt][3] = *(const uint32_t*)(sAh + o + 8 * ASTRIDE + 16);
                a[1][mt][0] = *(const uint32_t*)(sAl + o);
                a[1][mt][1] = *(const uint32_t*)(sAl + o + 8 * ASTRIDE);
                a[1][mt][2] = *(const uint32_t*)(sAl + o + 16);
                a[1][mt][3] = *(const uint32_t*)(sAl + o + 8 * ASTRIDE + 16);
            }
            uint32_t b[2][4][2];
#pragma unroll
            for (int nt = 0; nt < 4; ++nt) {
                const int n = wn * 32 + nt * 8 + gr;
                const int o = n * ASTRIDE + kb;
                b[0][nt][0] = *(const uint32_t*)(sBh + o);
                b[0][nt][1] = *(const uint32_t*)(sBh + o + 16);
                b[1][nt][0] = *(const uint32_t*)(sBl + o);
                b[1][nt][1] = *(const uint32_t*)(sBl + o + 16);
            }

            // hi*hi
#pragma unroll
            for (int mt = 0; mt < 4; ++mt)
#pragma unroll
                for (int nt = 0; nt < 4; ++nt)
                    mma16816(acc[mt][nt], a[0][mt], b[0][nt]);
            // hi*lo
#pragma unroll
            for (int mt = 0; mt < 4; ++mt)
#pragma unroll
                for (int nt = 0; nt < 4; ++nt)
                    mma16816(acc[mt][nt], a[0][mt], b[1][nt]);
            // lo*hi
#pragma unroll
            for (int mt = 0; mt < 4; ++mt)
#pragma unroll
                for (int nt = 0; nt < 4; ++nt)
                    mma16816(acc[mt][nt], a[1][mt], b[0][nt]);
        }
        __syncthreads();
    }

    // ---- epilogue: d0,d1 -> (gr, 2gc..+1); d2,d3 -> (gr+8, 2gc..+1) ----
#pragma unroll
    for (int mt = 0; mt < 4; ++mt) {
        const int r1 = row0 + wm * 64 + mt * 16 + gr;
        const int r2 = r1 + 8;
#pragma unroll
        for (int nt = 0; nt < 4; ++nt) {
            const int cc = col0 + wn * 32 + nt * 8 + 2 * gc;
            if (cc < Nn) {   // Nn % 8 == 0 -> atom all-or-nothing
                float bx = 0.f, by = 0.f;
                if (BIAS) { bx = bias[cc]; by = bias[cc + 1]; }
                if (r1 < M) {
                    float2 v = make_float2(acc[mt][nt][0] + bx, acc[mt][nt][1] + by);
                    *(float2*)&C[(size_t)r1 * Nn + cc] = v;
                }
                if (r2 < M) {
                    float2 v = make_float2(acc[mt][nt][2] + bx, acc[mt][nt][3] + by);
                    *(float2*)&C[(size_t)r2 * Nn + cc] = v;
                }
            }
        }
    }
}

// ============================================================================
// zero / scatter / GRU / FC (unchanged from R6-passing kernel)
// ============================================================================
__global__ void zero_k(float4* __restrict__ p, int n4)
{
    int i = blockIdx.x * blockDim.x + threadIdx.x;
    if (i < n4) p[i] = make_float4(0.f, 0.f, 0.f, 0.f);
}

__global__ __launch_bounds__(256)
void scatter_k(const float* __restrict__ m, const int* __restrict__ src,
               const int* __restrict__ dst, const float* __restrict__ ew,
               float* __restrict__ agg)
{
    int e = blockIdx.x;
    int t = threadIdx.x;
    if (t >= D4) return;
    int s = src[e];
    int d = dst[e];
    float w = ew[e];
    float4 v = *(const float4*)(m + (size_t)s * DD + t * 4);
    float* a = agg + (size_t)d * DD + t * 4;
    atomicAdd(a + 0, v.x * w);
    atomicAdd(a + 1, v.y * w);
    atomicAdd(a + 2, v.z * w);
    atomicAdd(a + 3, v.w * w);
}

__device__ __forceinline__ float gru1(float ir, float iz, float inn,
                                      float hr, float hz, float hn, float h)
{
    float r = 1.f / (1.f + expf(-(ir + hr)));
    float z = 1.f / (1.f + expf(-(iz + hz)));
    float n = tanhf(inn + r * hn);
    return (1.f - z) * n + z * h;
}

__global__ __launch_bounds__(256)
void gru_k(const float4* __restrict__ gi, const float4* __restrict__ gh,
           const float4* __restrict__ hin, float4* __restrict__ hout)
{
    int idx = blockIdx.x * blockDim.x + threadIdx.x;
    if (idx >= NN * D4) return;
    int n  = idx / D4;
    int dv = idx - n * D4;
    size_t b3 = (size_t)n * (3 * D4);
    float4 ir = gi[b3 + dv];
    float4 iz = gi[b3 + D4 + dv];
    float4 in_ = gi[b3 + 2 * D4 + dv];
    float4 hr = gh[b3 + dv];
    float4 hz = gh[b3 + D4 + dv];
    float4 hn = gh[b3 + 2 * D4 + dv];
    float4 h = hin[(size_t)n * D4 + dv];
    float4 o;
    o.x = gru1(ir.x, iz.x, in_.x, hr.x, hz.x, hn.x, h.x);
    o.y = gru1(ir.y, iz.y, in_.y, hr.y, hz.y, hn.y, h.y);
    o.z = gru1(ir.z, iz.z, in_.z, hr.z, hz.z, hn.z, h.z);
    o.w = gru1(ir.w, iz.w, in_.w, hr.w, hz.w, hn.w, h.w);
    hout[(size_t)n * D4 + dv] = o;
}

__global__ __launch_bounds__(256)
void fc_k(const float* __restrict__ h, const float* __restrict__ fw,
          const float* __restrict__ fb, float* __restrict__ out)
{
    int warp = (blockIdx.x * 256 + threadIdx.x) >> 5;
    int lane = threadIdx.x & 31;
    if (warp >= NN) return;
    const float4* h4 = (const float4*)(h + (size_t)warp * DD);
    const float4* w4 = (const float4*)fw;
    float s = 0.f;
    for (int i = lane; i < D4; i += 32) {
        float4 hv = h4[i];
        float4 wv = w4[i];
        s += fmaxf(hv.x, 0.f) * wv.x + fmaxf(hv.y, 0.f) * wv.y +
             fmaxf(hv.z, 0.f) * wv.z + fmaxf(hv.w, 0.f) * wv.w;
    }
#pragma unroll
    for (int off = 16; off; off >>= 1)
        s += __shfl_down_sync(0xffffffffu, s, off);
    if (lane == 0) out[warp] = s + fb[0];
}

// ============================================================================
// launch
// ============================================================================
extern "C" void kernel_launch(void* const* d_in, const int* in_sizes, int n_in,
                              void* d_out, int out_size)
{
    const float* x      = (const float*)d_in[0];
    const int*   ei     = (const int*)  d_in[1];
    const float* ew     = (const float*)d_in[2];
    const float* weight = (const float*)d_in[3];
    const float* w_ih   = (const float*)d_in[4];
    const float* w_hh   = (const float*)d_in[5];
    const float* b_ih   = (const float*)d_in[6];
    const float* b_hh   = (const float*)d_in[7];
    const float* fc_w   = (const float*)d_in[8];
    const float* fc_b   = (const float*)d_in[9];
    float* out = (float*)d_out;

    float *pm, *pagg, *pgi, *pgh, *ph;
    __nv_bfloat16 *pa_hi, *pa_lo, *ph_hi, *ph_lo;
    __nv_bfloat16 *pwih_hi, *pwih_lo, *pwhh_hi, *pwhh_lo, *pwt_hi, *pwt_lo;
    cudaGetSymbolAddress((void**)&pm,     g_m);
    cudaGetSymbolAddress((void**)&pagg,   g_agg);
    cudaGetSymbolAddress((void**)&pgi,    g_gi);
    cudaGetSymbolAddress((void**)&pgh,    g_gh);
    cudaGetSymbolAddress((void**)&ph,     g_h);
    cudaGetSymbolAddress((void**)&pa_hi,  g_a_hi);
    cudaGetSymbolAddress((void**)&pa_lo,  g_a_lo);
    cudaGetSymbolAddress((void**)&ph_hi,  g_h_hi);
    cudaGetSymbolAddress((void**)&ph_lo,  g_h_lo);
    cudaGetSymbolAddress((void**)&pwih_hi, g_wih_hi);
    cudaGetSymbolAddress((void**)&pwih_lo, g_wih_lo);
    cudaGetSymbolAddress((void**)&pwhh_hi, g_whh_hi);
    cudaGetSymbolAddress((void**)&pwhh_lo, g_whh_lo);
    cudaGetSymbolAddress((void**)&pwt_hi,  g_wt_hi);
    cudaGetSymbolAddress((void**)&pwt_lo,  g_wt_lo);

    const int* src = ei;
    const int* dst = ei + EE;

    cudaFuncSetAttribute(mma_gemm_k<false>,
                         cudaFuncAttributeMaxDynamicSharedMemorySize, SMEM_DYN);
    cudaFuncSetAttribute(mma_gemm_k<true>,
                         cudaFuncAttributeMaxDynamicSharedMemorySize, SMEM_DYN);

    // ---- one-time weight conversions ----
    conv_split_k<<<DIVUP(TD * (KP / 4), 256), 256>>>(w_ih, pwih_hi, pwih_lo, TD, DD);
    conv_split_k<<<DIVUP(TD * (KP / 4), 256), 256>>>(w_hh, pwhh_hi, pwhh_lo, TD, DD);
    for (int l = 0; l < NLAYERS; ++l)
        convT_split_k<<<DIVUP(DD * (KP / 4), 256), 256>>>(
            weight + (size_t)l * DD * DD,
            pwt_hi + (size_t)l * DD * KP, pwt_lo + (size_t)l * DD * KP);

    dim3 grid1(DIVUP(DD, 128), DIVUP(NN, 128));   // 8 x 157
    dim3 grid3(DIVUP(TD, 128), DIVUP(NN, 128));   // 24 x 157
    const int ew_blocks = DIVUP(NN * D4, 256);

    for (int l = 0; l < NLAYERS; ++l) {
        const float* hin = (l == 0) ? x : ph;

        // split hin -> bf16 hi/lo (feeds both m-GEMM and gh-GEMM)
        conv_split_k<<<DIVUP(NN * (KP / 4), 256), 256>>>(hin, ph_hi, ph_lo, NN, DD);

        // m = h @ W[l]  (W transposed+split in prep)
        mma_gemm_k<false><<<grid1, 256, SMEM_DYN>>>(
            ph_hi, ph_lo,
            pwt_hi + (size_t)l * DD * KP, pwt_lo + (size_t)l * DD * KP,
            nullptr, pm, NN, DD);

        // agg = scatter_add(m[src] * ew, dst)
        zero_k<<<ew_blocks, 256>>>((float4*)pagg, NN * D4);
        scatter_k<<<EE, 256>>>(pm, src, dst, ew, pagg);

        // split agg
        conv_split_k<<<DIVUP(NN * (KP / 4), 256), 256>>>(pagg, pa_hi, pa_lo, NN, DD);

        // gi = agg @ w_ih^T + b_ih ; gh = h @ w_hh^T + b_hh
        mma_gemm_k<true><<<grid3, 256, SMEM_DYN>>>(
            pa_hi, pa_lo, pwih_hi, pwih_lo, b_ih, pgi, NN, TD);
        mma_gemm_k<true><<<grid3, 256, SMEM_DYN>>>(
            ph_hi, ph_lo, pwhh_hi, pwhh_lo, b_hh, pgh, NN, TD);

        // h = GRU(gi, gh, h)
        gru_k<<<ew_blocks, 256>>>((const float4*)pgi, (const float4*)pgh,
                                  (const float4*)hin, (float4*)ph);
    }

    // out = relu(h) @ fc_w^T + fc_b
    fc_k<<<DIVUP(NN, 8), 256>>>(ph, fc_w, fc_b, out);
}

// round 12
// speedup vs baseline: 2.6425x; 1.1272x over previous
#include <cuda_runtime.h>
#include <cuda_bf16.h>
#include <math.h>
#include <stdint.h>

// Problem constants (fixed by the reference)
#define NN 20000          // nodes
#define EE 160000         // edges
#define DD 1000           // feature dim
#define TD 3000           // 3*D
#define NLAYERS 3
#define D4 250            // D/4
#define KP 1024           // K padded to multiple of 64
#define KP8 (KP/8)        // uint4 (8 bf16) per padded row = 128
#define NCHUNK (KP/64)    // 16

#define DIVUP(a,b) (((a)+(b)-1)/(b))

// ---------------- scratch (device globals: sanctioned no-alloc path) --------
__device__ float g_m  [(size_t)NN * DD];   // 80 MB
__device__ float g_gi [(size_t)NN * TD];   // 240 MB
__device__ float g_gh [(size_t)NN * TD];   // 240 MB
__device__ float g_h  [(size_t)NN * DD];   // 80 MB
// bf16 hi/lo split operand buffers (K padded to KP; pad cols stay zero from
// static zero-initialization — kernels only ever write cols [0, DD))
__device__ __nv_bfloat16 g_a_hi [(size_t)NN * KP];
__device__ __nv_bfloat16 g_a_lo [(size_t)NN * KP];
__device__ __nv_bfloat16 g_h_hi [(size_t)NN * KP];
__device__ __nv_bfloat16 g_h_lo [(size_t)NN * KP];
__device__ __nv_bfloat16 g_wih_hi[(size_t)TD * KP];
__device__ __nv_bfloat16 g_wih_lo[(size_t)TD * KP];
__device__ __nv_bfloat16 g_whh_hi[(size_t)TD * KP];
__device__ __nv_bfloat16 g_whh_lo[(size_t)TD * KP];
__device__ __nv_bfloat16 g_wt_hi [(size_t)NLAYERS * DD * KP];
__device__ __nv_bfloat16 g_wt_lo [(size_t)NLAYERS * DD * KP];
// CSR of edge list keyed by dst (rebuilt every launch; deterministic inputs)
__device__ int g_deg[NN];
__device__ int g_off[NN + 1];
__device__ int g_cur[NN];
__device__ int g_eid[EE];

// ====================== helpers (sm_80-baseline PTX only) ===================
__device__ __forceinline__ uint32_t smem_u32(const void* p) {
    uint32_t a;
    asm("{ .reg .u64 t; cvta.to.shared.u64 t, %1; cvt.u32.u64 %0, t; }"
        : "=r"(a) : "l"(p));
    return a;
}
__device__ __forceinline__ void cp16(uint32_t s, const void* g, uint32_t sz) {
    asm volatile("cp.async.cg.shared.global [%0], [%1], 16, %2;"
                 :: "r"(s), "l"(g), "r"(sz) : "memory");
}
#define CP_COMMIT() asm volatile("cp.async.commit_group;" ::: "memory")
#define CP_WAIT1()  asm volatile("cp.async.wait_group 1;" ::: "memory")
#define CP_WAIT0()  asm volatile("cp.async.wait_group 0;" ::: "memory")

// D += A(16x16 bf16, row) @ B(16x8 bf16, col)
__device__ __forceinline__ void mma16816(float* d, const uint32_t* a, const uint32_t* b) {
    asm volatile(
        "mma.sync.aligned.m16n8k16.row.col.f32.bf16.bf16.f32 "
        "{%0,%1,%2,%3}, {%4,%5,%6,%7}, {%8,%9}, {%0,%1,%2,%3};"
        : "+f"(d[0]), "+f"(d[1]), "+f"(d[2]), "+f"(d[3])
        : "r"(a[0]), "r"(a[1]), "r"(a[2]), "r"(a[3]), "r"(b[0]), "r"(b[1]));
}

__device__ __forceinline__ uint2 split_pack4(float4 v, uint2* lo_out) {
    __nv_bfloat16 h0 = __float2bfloat16(v.x), h1 = __float2bfloat16(v.y);
    __nv_bfloat16 h2 = __float2bfloat16(v.z), h3 = __float2bfloat16(v.w);
    __nv_bfloat16 l0 = __float2bfloat16(v.x - __bfloat162float(h0));
    __nv_bfloat16 l1 = __float2bfloat16(v.y - __bfloat162float(h1));
    __nv_bfloat16 l2 = __float2bfloat16(v.z - __bfloat162float(h2));
    __nv_bfloat16 l3 = __float2bfloat16(v.w - __bfloat162float(h3));
    uint2 ph, pl;
    ph.x = ((uint32_t)__bfloat16_as_ushort(h1) << 16) | __bfloat16_as_ushort(h0);
    ph.y = ((uint32_t)__bfloat16_as_ushort(h3) << 16) | __bfloat16_as_ushort(h2);
    pl.x = ((uint32_t)__bfloat16_as_ushort(l1) << 16) | __bfloat16_as_ushort(l0);
    pl.y = ((uint32_t)__bfloat16_as_ushort(l3) << 16) | __bfloat16_as_ushort(l2);
    *lo_out = pl;
    return ph;
}

// ============================================================================
// fp32 -> bf16 hi/lo split, row-major [M][Kin] -> [M][KP] (tail zero)
// ============================================================================
__global__ __launch_bounds__(256)
void conv_split_k(const float* __restrict__ in, __nv_bfloat16* __restrict__ hi,
                  __nv_bfloat16* __restrict__ lo, int M, int Kin)
{
    int idx = blockIdx.x * blockDim.x + threadIdx.x;   // over M * KP/4
    if (idx >= M * (KP / 4)) return;
    int r  = idx / (KP / 4);
    int c  = (idx - r * (KP / 4)) * 4;
    float4 v = make_float4(0.f, 0.f, 0.f, 0.f);
    if (c + 3 < Kin) v = *(const float4*)(in + (size_t)r * Kin + c);
    uint2 pl;
    uint2 ph = split_pack4(v, &pl);
    *(uint2*)(hi + (size_t)r * KP + c) = ph;
    *(uint2*)(lo + (size_t)r * KP + c) = pl;
}

// ============================================================================
// weight[l] is [K=1000][N=1000] (N contiguous); emit transposed split
// ============================================================================
__global__ __launch_bounds__(256)
void convT_split_k(const float* __restrict__ w, __nv_bfloat16* __restrict__ hi,
                   __nv_bfloat16* __restrict__ lo)
{
    int idx = blockIdx.x * blockDim.x + threadIdx.x;   // over DD * KP/4
    if (idx >= DD * (KP / 4)) return;
    int n = idx / (KP / 4);
    int k = (idx - n * (KP / 4)) * 4;
    float4 v = make_float4(0.f, 0.f, 0.f, 0.f);
    if (k + 3 < DD) {
        v.x = w[(size_t)(k    ) * DD + n];
        v.y = w[(size_t)(k + 1) * DD + n];
        v.z = w[(size_t)(k + 2) * DD + n];
        v.w = w[(size_t)(k + 3) * DD + n];
    }
    uint2 pl;
    uint2 ph = split_pack4(v, &pl);
    *(uint2*)(hi + (size_t)n * KP + k) = ph;
    *(uint2*)(lo + (size_t)n * KP + k) = pl;
}

// ============================================================================
// CSR build (per launch; deterministic edge list)
// ============================================================================
__global__ void zero_deg_k(int* __restrict__ deg)
{
    int i = blockIdx.x * blockDim.x + threadIdx.x;
    if (i < NN) deg[i] = 0;
}
__global__ void hist_k(const int* __restrict__ dst, int* __restrict__ deg)
{
    int e = blockIdx.x * blockDim.x + threadIdx.x;
    if (e < EE) atomicAdd(&deg[dst[e]], 1);
}
// single-block exclusive scan over NN degrees -> off[NN+1], cur[] = off copy
__global__ __launch_bounds__(1024)
void scan_k(const int* __restrict__ deg, int* __restrict__ off,
            int* __restrict__ cur)
{
    __shared__ int part[1024];
    const int tid = threadIdx.x;
    const int per = DIVUP(NN, 1024);     // 20
    const int base = tid * per;
    int loc[DIVUP(NN, 1024)];
    int s = 0;
#pragma unroll
    for (int i = 0; i < per; ++i) {
        int idx = base + i;
        int v = (idx < NN) ? deg[idx] : 0;
        loc[i] = v;
        s += v;
    }
    part[tid] = s;
    __syncthreads();
    for (int d = 1; d < 1024; d <<= 1) {
        int v = (tid >= d) ? part[tid - d] : 0;
        __syncthreads();
        part[tid] += v;
        __syncthreads();
    }
    int run = part[tid] - s;    // exclusive prefix of this thread's span
#pragma unroll
    for (int i = 0; i < per; ++i) {
        int idx = base + i;
        if (idx < NN) { off[idx] = run; cur[idx] = run; run += loc[i]; }
    }
    if (tid == 1023) off[NN] = run;
}
__global__ void fill_k(const int* __restrict__ dst, int* __restrict__ cur,
                       int* __restrict__ eid)
{
    int e = blockIdx.x * blockDim.x + threadIdx.x;
    if (e < EE) {
        int p = atomicAdd(&cur[dst[e]], 1);
        eid[p] = e;
    }
}

// ============================================================================
// CSR scatter: block per dst node; agg[n] = sum_e w_e * m[src_e]
// Accumulate in registers, emit bf16 hi/lo split directly (no fp32 agg,
// no atomics, no zero pass). Pad cols [DD, KP) remain statically zero.
// ============================================================================
__global__ __launch_bounds__(256)
void scatter_csr_k(const float* __restrict__ m, const int* __restrict__ src,
                   const float* __restrict__ ew, const int* __restrict__ off,
                   const int* __restrict__ eid,
                   __nv_bfloat16* __restrict__ ahi, __nv_bfloat16* __restrict__ alo)
{
    const int n = blockIdx.x;
    const int t = threadIdx.x;
    if (t >= D4) return;
    const int s0 = off[n];
    const int s1 = off[n + 1];
    float4 acc = make_float4(0.f, 0.f, 0.f, 0.f);
    for (int i = s0; i < s1; ++i) {
        const int e = eid[i];
        const int s = src[e];
        const float w = ew[e];
        const float4 v = *(const float4*)(m + (size_t)s * DD + t * 4);
        acc.x += v.x * w;
        acc.y += v.y * w;
        acc.z += v.z * w;
        acc.w += v.w * w;
    }
    uint2 pl;
    uint2 ph = split_pack4(acc, &pl);
    *(uint2*)(ahi + (size_t)n * KP + t * 4) = ph;
    *(uint2*)(alo + (size_t)n * KP + t * 4) = pl;
}

// ============================================================================
// mma.sync GEMM: C[M,Nn] = Ahi@Bhi^T + Ahi@Blo^T + Alo@Bhi^T (+ bias)
// (unchanged from R11-passing kernel)
// ============================================================================
#define ASTRIDE 144
#define TILE_SB (128 * ASTRIDE)
#define STAGE_SB (4 * TILE_SB)
#define SMEM_DYN (2 * STAGE_SB)

template<bool BIAS>
__global__ __launch_bounds__(256, 1)
void mma_gemm_k(const __nv_bfloat16* __restrict__ Ahi, const __nv_bfloat16* __restrict__ Alo,
                const __nv_bfloat16* __restrict__ Bhi, const __nv_bfloat16* __restrict__ Blo,
                const float* __restrict__ bias, float* __restrict__ C,
                int M, int Nn)
{
    extern __shared__ char smem[];
    const int tid  = threadIdx.x;
    const int lane = tid & 31;
    const int wid  = tid >> 5;
    const int gr   = lane >> 2;
    const int gc   = lane & 3;
    const int wm   = wid >> 2;
    const int wn   = wid & 3;
    const int row0 = blockIdx.y * 128;
    const int col0 = blockIdx.x * 128;

    const uint4* pAhi = (const uint4*)Ahi;
    const uint4* pAlo = (const uint4*)Alo;
    const uint4* pBhi = (const uint4*)Bhi;
    const uint4* pBlo = (const uint4*)Blo;

    const uint32_t sbase = smem_u32(smem);

    float acc[4][4][4];
#pragma unroll
    for (int i = 0; i < 4; i++)
#pragma unroll
        for (int j = 0; j < 4; j++)
#pragma unroll
            for (int k = 0; k < 4; k++) acc[i][j][k] = 0.f;

    const int lrow = tid >> 3;
    const int lu   = tid & 7;

    auto load_chunk = [&](int c, int stage) {
        const uint32_t st = sbase + stage * STAGE_SB;
        const int k0u = c * 8;
#pragma unroll
        for (int it = 0; it < 4; ++it) {
            const int rr = lrow + it * 32;
            const uint32_t soff = (uint32_t)(rr * ASTRIDE + lu * 16);
            const int ar = row0 + rr;
            const uint32_t asz = (ar < M) ? 16u : 0u;
            const size_t ga = (size_t)((ar < M) ? ar : 0) * KP8 + (k0u + lu);
            cp16(st + 0 * TILE_SB + soff, pAhi + ga, asz);
            cp16(st + 1 * TILE_SB + soff, pAlo + ga, asz);
            const int br = col0 + rr;
            const uint32_t bsz = (br < Nn) ? 16u : 0u;
            const size_t gb = (size_t)((br < Nn) ? br : 0) * KP8 + (k0u + lu);
            cp16(st + 2 * TILE_SB + soff, pBhi + gb, bsz);
            cp16(st + 3 * TILE_SB + soff, pBlo + gb, bsz);
        }
        CP_COMMIT();
    };

    load_chunk(0, 0);

    for (int c = 0; c < NCHUNK; ++c) {
        if (c + 1 < NCHUNK) {
            load_chunk(c + 1, (c + 1) & 1);
            CP_WAIT1();
        } else {
            CP_WAIT0();
        }
        __syncthreads();

        const char* st = smem + (c & 1) * STAGE_SB;
        const char* sAh = st;
        const char* sAl = st + TILE_SB;
        const char* sBh = st + 2 * TILE_SB;
        const char* sBl = st + 3 * TILE_SB;

#pragma unroll
        for (int ks = 0; ks < 4; ++ks) {
            const int kb = ks * 32 + gc * 4;

            uint32_t a[2][4][4];
#pragma unroll
            for (int mt = 0; mt < 4; ++mt) {
                const int r = wm * 64 + mt * 16 + gr;
                const int o = r * ASTRIDE + kb;
                a[0][mt][0] = *(const uint32_t*)(sAh + o);
                a[0][mt][1] = *(const uint32_t*)(sAh + o + 8 * ASTRIDE);
                a[0][mt][2] = *(const uint32_t*)(sAh + o + 16);
                a[0][mt][3] = *(const uint32_t*)(sAh + o + 8 * ASTRIDE + 16);
                a[1][mt][0] = *(const uint32_t*)(sAl + o);
                a[1][mt][1] = *(const uint32_t*)(sAl + o + 8 * ASTRIDE);
                a[1][mt][2] = *(const uint32_t*)(sAl + o + 16);
                a[1][mt][3] = *(const uint32_t*)(sAl + o + 8 * ASTRIDE + 16);
            }
            uint32_t b[2][4][2];
#pragma unroll
            for (int nt = 0; nt < 4; ++nt) {
                const int n = wn * 32 + nt * 8 + gr;
                const int o = n * ASTRIDE + kb;
                b[0][nt][0] = *(const uint32_t*)(sBh + o);
                b[0][nt][1] = *(const uint32_t*)(sBh + o + 16);
                b[1][nt][0] = *(const uint32_t*)(sBl + o);
                b[1][nt][1] = *(const uint32_t*)(sBl + o + 16);
            }

#pragma unroll
            for (int mt = 0; mt < 4; ++mt)
#pragma unroll
                for (int nt = 0; nt < 4; ++nt)
                    mma16816(acc[mt][nt], a[0][mt], b[0][nt]);
#pragma unroll
            for (int mt = 0; mt < 4; ++mt)
#pragma unroll
                for (int nt = 0; nt < 4; ++nt)
                    mma16816(acc[mt][nt], a[0][mt], b[1][nt]);
#pragma unroll
            for (int mt = 0; mt < 4; ++mt)
#pragma unroll
                for (int nt = 0; nt < 4; ++nt)
                    mma16816(acc[mt][nt], a[1][mt], b[0][nt]);
        }
        __syncthreads();
    }

#pragma unroll
    for (int mt = 0; mt < 4; ++mt) {
        const int r1 = row0 + wm * 64 + mt * 16 + gr;
        const int r2 = r1 + 8;
#pragma unroll
        for (int nt = 0; nt < 4; ++nt) {
            const int cc = col0 + wn * 32 + nt * 8 + 2 * gc;
            if (cc < Nn) {
                float bx = 0.f, by = 0.f;
                if (BIAS) { bx = bias[cc]; by = bias[cc + 1]; }
                if (r1 < M) {
                    float2 v = make_float2(acc[mt][nt][0] + bx, acc[mt][nt][1] + by);
                    *(float2*)&C[(size_t)r1 * Nn + cc] = v;
                }
                if (r2 < M) {
                    float2 v = make_float2(acc[mt][nt][2] + bx, acc[mt][nt][3] + by);
                    *(float2*)&C[(size_t)r2 * Nn + cc] = v;
                }
            }
        }
    }
}

// ============================================================================
// GRU elementwise, fused with bf16 hi/lo split of the new h
// ============================================================================
__device__ __forceinline__ float gru1(float ir, float iz, float inn,
                                      float hr, float hz, float hn, float h)
{
    float r = 1.f / (1.f + expf(-(ir + hr)));
    float z = 1.f / (1.f + expf(-(iz + hz)));
    float n = tanhf(inn + r * hn);
    return (1.f - z) * n + z * h;
}

__global__ __launch_bounds__(256)
void gru_split_k(const float4* __restrict__ gi, const float4* __restrict__ gh,
                 const float4* __restrict__ hin, float4* __restrict__ hout,
                 __nv_bfloat16* __restrict__ hhi, __nv_bfloat16* __restrict__ hlo)
{
    int idx = blockIdx.x * blockDim.x + threadIdx.x;
    if (idx >= NN * D4) return;
    int n  = idx / D4;
    int dv = idx - n * D4;
    size_t b3 = (size_t)n * (3 * D4);
    float4 ir = gi[b3 + dv];
    float4 iz = gi[b3 + D4 + dv];
    float4 in_ = gi[b3 + 2 * D4 + dv];
    float4 hr = gh[b3 + dv];
    float4 hz = gh[b3 + D4 + dv];
    float4 hn = gh[b3 + 2 * D4 + dv];
    float4 h = hin[(size_t)n * D4 + dv];
    float4 o;
    o.x = gru1(ir.x, iz.x, in_.x, hr.x, hz.x, hn.x, h.x);
    o.y = gru1(ir.y, iz.y, in_.y, hr.y, hz.y, hn.y, h.y);
    o.z = gru1(ir.z, iz.z, in_.z, hr.z, hz.z, hn.z, h.z);
    o.w = gru1(ir.w, iz.w, in_.w, hr.w, hz.w, hn.w, h.w);
    hout[(size_t)n * D4 + dv] = o;
    uint2 pl;
    uint2 ph = split_pack4(o, &pl);
    *(uint2*)(hhi + (size_t)n * KP + dv * 4) = ph;
    *(uint2*)(hlo + (size_t)n * KP + dv * 4) = pl;
}

// ============================================================================
// Final: out[n] = sum_d relu(h[n,d]) * fc_w[d] + fc_b   (warp per node)
// ============================================================================
__global__ __launch_bounds__(256)
void fc_k(const float* __restrict__ h, const float* __restrict__ fw,
          const float* __restrict__ fb, float* __restrict__ out)
{
    int warp = (blockIdx.x * 256 + threadIdx.x) >> 5;
    int lane = threadIdx.x & 31;
    if (warp >= NN) return;
    const float4* h4 = (const float4*)(h + (size_t)warp * DD);
    const float4* w4 = (const float4*)fw;
    float s = 0.f;
    for (int i = lane; i < D4; i += 32) {
        float4 hv = h4[i];
        float4 wv = w4[i];
        s += fmaxf(hv.x, 0.f) * wv.x + fmaxf(hv.y, 0.f) * wv.y +
             fmaxf(hv.z, 0.f) * wv.z + fmaxf(hv.w, 0.f) * wv.w;
    }
#pragma unroll
    for (int off = 16; off; off >>= 1)
        s += __shfl_down_sync(0xffffffffu, s, off);
    if (lane == 0) out[warp] = s + fb[0];
}

// ============================================================================
// launch
// ============================================================================
extern "C" void kernel_launch(void* const* d_in, const int* in_sizes, int n_in,
                              void* d_out, int out_size)
{
    const float* x      = (const float*)d_in[0];
    const int*   ei     = (const int*)  d_in[1];
    const float* ew     = (const float*)d_in[2];
    const float* weight = (const float*)d_in[3];
    const float* w_ih   = (const float*)d_in[4];
    const float* w_hh   = (const float*)d_in[5];
    const float* b_ih   = (const float*)d_in[6];
    const float* b_hh   = (const float*)d_in[7];
    const float* fc_w   = (const float*)d_in[8];
    const float* fc_b   = (const float*)d_in[9];
    float* out = (float*)d_out;

    float *pm, *pgi, *pgh, *ph;
    __nv_bfloat16 *pa_hi, *pa_lo, *ph_hi, *ph_lo;
    __nv_bfloat16 *pwih_hi, *pwih_lo, *pwhh_hi, *pwhh_lo, *pwt_hi, *pwt_lo;
    int *pdeg, *poff, *pcur, *peid;
    cudaGetSymbolAddress((void**)&pm,     g_m);
    cudaGetSymbolAddress((void**)&pgi,    g_gi);
    cudaGetSymbolAddress((void**)&pgh,    g_gh);
    cudaGetSymbolAddress((void**)&ph,     g_h);
    cudaGetSymbolAddress((void**)&pa_hi,  g_a_hi);
    cudaGetSymbolAddress((void**)&pa_lo,  g_a_lo);
    cudaGetSymbolAddress((void**)&ph_hi,  g_h_hi);
    cudaGetSymbolAddress((void**)&ph_lo,  g_h_lo);
    cudaGetSymbolAddress((void**)&pwih_hi, g_wih_hi);
    cudaGetSymbolAddress((void**)&pwih_lo, g_wih_lo);
    cudaGetSymbolAddress((void**)&pwhh_hi, g_whh_hi);
    cudaGetSymbolAddress((void**)&pwhh_lo, g_whh_lo);
    cudaGetSymbolAddress((void**)&pwt_hi,  g_wt_hi);
    cudaGetSymbolAddress((void**)&pwt_lo,  g_wt_lo);
    cudaGetSymbolAddress((void**)&pdeg,   g_deg);
    cudaGetSymbolAddress((void**)&poff,   g_off);
    cudaGetSymbolAddress((void**)&pcur,   g_cur);
    cudaGetSymbolAddress((void**)&peid,   g_eid);

    const int* src = ei;
    const int* dst = ei + EE;

    cudaFuncSetAttribute(mma_gemm_k<false>,
                         cudaFuncAttributeMaxDynamicSharedMemorySize, SMEM_DYN);
    cudaFuncSetAttribute(mma_gemm_k<true>,
                         cudaFuncAttributeMaxDynamicSharedMemorySize, SMEM_DYN);

    // ---- CSR build (edges fixed across layers) ----
    zero_deg_k<<<DIVUP(NN, 256), 256>>>(pdeg);
    hist_k<<<DIVUP(EE, 256), 256>>>(dst, pdeg);
    scan_k<<<1, 1024>>>(pdeg, poff, pcur);
    fill_k<<<DIVUP(EE, 256), 256>>>(dst, pcur, peid);

    // ---- weight conversions ----
    conv_split_k<<<DIVUP(TD * (KP / 4), 256), 256>>>(w_ih, pwih_hi, pwih_lo, TD, DD);
    conv_split_k<<<DIVUP(TD * (KP / 4), 256), 256>>>(w_hh, pwhh_hi, pwhh_lo, TD, DD);
    for (int l = 0; l < NLAYERS; ++l)
        convT_split_k<<<DIVUP(DD * (KP / 4), 256), 256>>>(
            weight + (size_t)l * DD * DD,
            pwt_hi + (size_t)l * DD * KP, pwt_lo + (size_t)l * DD * KP);

    // split x for layer 0 (later layers get the split from gru_split_k)
    conv_split_k<<<DIVUP(NN * (KP / 4), 256), 256>>>(x, ph_hi, ph_lo, NN, DD);

    dim3 grid1(DIVUP(DD, 128), DIVUP(NN, 128));   // 8 x 157
    dim3 grid3(DIVUP(TD, 128), DIVUP(NN, 128));   // 24 x 157
    const int ew_blocks = DIVUP(NN * D4, 256);

    for (int l = 0; l < NLAYERS; ++l) {
        const float* hin = (l == 0) ? x : ph;

        // m = h @ W[l]
        mma_gemm_k<false><<<grid1, 256, SMEM_DYN>>>(
            ph_hi, ph_lo,
            pwt_hi + (size_t)l * DD * KP, pwt_lo + (size_t)l * DD * KP,
            nullptr, pm, NN, DD);

        // agg = scatter_add(m[src] * ew, dst)  -> bf16 split directly
        scatter_csr_k<<<NN, 256>>>(pm, src, ew, poff, peid, pa_hi, pa_lo);

        // gi = agg @ w_ih^T + b_ih ; gh = h @ w_hh^T + b_hh
        mma_gemm_k<true><<<grid3, 256, SMEM_DYN>>>(
            pa_hi, pa_lo, pwih_hi, pwih_lo, b_ih, pgi, NN, TD);
        mma_gemm_k<true><<<grid3, 256, SMEM_DYN>>>(
            ph_hi, ph_lo, pwhh_hi, pwhh_lo, b_hh, pgh, NN, TD);

        // h = GRU(gi, gh, h), fused with split for next layer's GEMMs
        gru_split_k<<<ew_blocks, 256>>>((const float4*)pgi, (const float4*)pgh,
                                        (const float4*)hin, (float4*)ph,
                                        ph_hi, ph_lo);
    }

    // out = relu(h) @ fc_w^T + fc_b
    fc_k<<<DIVUP(NN, 8), 256>>>(ph, fc_w, fc_b, out);
}

// round 13
// speedup vs baseline: 2.8268x; 1.0697x over previous
#include <cuda_runtime.h>
#include <cuda_bf16.h>
#include <math.h>
#include <stdint.h>

// Problem constants (fixed by the reference)
#define NN 20000          // nodes
#define EE 160000         // edges
#define DD 1000           // feature dim
#define TD 3000           // 3*D
#define NLAYERS 3
#define D4 250            // D/4
#define KP 1024           // K padded to multiple of 64
#define KP8 (KP/8)        // uint4 (8 bf16) per padded row = 128
#define NCHUNK2 (KP/32)   // 32 chunks of K=32

#define DIVUP(a,b) (((a)+(b)-1)/(b))

// ---------------- scratch (device globals: sanctioned no-alloc path) --------
__device__ float g_m  [(size_t)NN * DD];   // 80 MB
__device__ float g_gi [(size_t)NN * TD];   // 240 MB
__device__ float g_gh [(size_t)NN * TD];   // 240 MB
__device__ float g_h  [(size_t)NN * DD];   // 80 MB
// bf16 hi/lo split operand buffers (K padded to KP; pad cols stay zero from
// static zero-initialization — kernels only ever write cols [0, DD))
__device__ __nv_bfloat16 g_a_hi [(size_t)NN * KP];
__device__ __nv_bfloat16 g_a_lo [(size_t)NN * KP];
__device__ __nv_bfloat16 g_h_hi [(size_t)NN * KP];
__device__ __nv_bfloat16 g_h_lo [(size_t)NN * KP];
__device__ __nv_bfloat16 g_wih_hi[(size_t)TD * KP];
__device__ __nv_bfloat16 g_wih_lo[(size_t)TD * KP];
__device__ __nv_bfloat16 g_whh_hi[(size_t)TD * KP];
__device__ __nv_bfloat16 g_whh_lo[(size_t)TD * KP];
__device__ __nv_bfloat16 g_wt_hi [(size_t)NLAYERS * DD * KP];
__device__ __nv_bfloat16 g_wt_lo [(size_t)NLAYERS * DD * KP];
// CSR of edge list keyed by dst (rebuilt every launch; deterministic inputs)
__device__ int g_deg[NN];
__device__ int g_off[NN + 1];
__device__ int g_cur[NN];
__device__ int g_eid[EE];

// ====================== helpers (sm_80-baseline PTX only) ===================
__device__ __forceinline__ uint32_t smem_u32(const void* p) {
    uint32_t a;
    asm("{ .reg .u64 t; cvta.to.shared.u64 t, %1; cvt.u32.u64 %0, t; }"
        : "=r"(a) : "l"(p));
    return a;
}
__device__ __forceinline__ void cp16(uint32_t s, const void* g, uint32_t sz) {
    asm volatile("cp.async.cg.shared.global [%0], [%1], 16, %2;"
                 :: "r"(s), "l"(g), "r"(sz) : "memory");
}
#define CP_COMMIT() asm volatile("cp.async.commit_group;" ::: "memory")
#define CP_WAIT1()  asm volatile("cp.async.wait_group 1;" ::: "memory")
#define CP_WAIT0()  asm volatile("cp.async.wait_group 0;" ::: "memory")

// D += A(16x16 bf16, row) @ B(16x8 bf16, col)
__device__ __forceinline__ void mma16816(float* d, const uint32_t* a, const uint32_t* b) {
    asm volatile(
        "mma.sync.aligned.m16n8k16.row.col.f32.bf16.bf16.f32 "
        "{%0,%1,%2,%3}, {%4,%5,%6,%7}, {%8,%9}, {%0,%1,%2,%3};"
        : "+f"(d[0]), "+f"(d[1]), "+f"(d[2]), "+f"(d[3])
        : "r"(a[0]), "r"(a[1]), "r"(a[2]), "r"(a[3]), "r"(b[0]), "r"(b[1]));
}
// ldmatrix x4: four 8x8 b16 tiles, one address per lane
__device__ __forceinline__ void ldsm4(uint32_t* r, uint32_t addr) {
    asm volatile("ldmatrix.sync.aligned.m8n8.x4.shared.b16 {%0,%1,%2,%3}, [%4];"
        : "=r"(r[0]), "=r"(r[1]), "=r"(r[2]), "=r"(r[3]) : "r"(addr));
}

__device__ __forceinline__ uint2 split_pack4(float4 v, uint2* lo_out) {
    __nv_bfloat16 h0 = __float2bfloat16(v.x), h1 = __float2bfloat16(v.y);
    __nv_bfloat16 h2 = __float2bfloat16(v.z), h3 = __float2bfloat16(v.w);
    __nv_bfloat16 l0 = __float2bfloat16(v.x - __bfloat162float(h0));
    __nv_bfloat16 l1 = __float2bfloat16(v.y - __bfloat162float(h1));
    __nv_bfloat16 l2 = __float2bfloat16(v.z - __bfloat162float(h2));
    __nv_bfloat16 l3 = __float2bfloat16(v.w - __bfloat162float(h3));
    uint2 ph, pl;
    ph.x = ((uint32_t)__bfloat16_as_ushort(h1) << 16) | __bfloat16_as_ushort(h0);
    ph.y = ((uint32_t)__bfloat16_as_ushort(h3) << 16) | __bfloat16_as_ushort(h2);
    pl.x = ((uint32_t)__bfloat16_as_ushort(l1) << 16) | __bfloat16_as_ushort(l0);
    pl.y = ((uint32_t)__bfloat16_as_ushort(l3) << 16) | __bfloat16_as_ushort(l2);
    *lo_out = pl;
    return ph;
}

// ============================================================================
// fp32 -> bf16 hi/lo split, row-major [M][Kin] -> [M][KP] (tail zero)
// ============================================================================
__global__ __launch_bounds__(256)
void conv_split_k(const float* __restrict__ in, __nv_bfloat16* __restrict__ hi,
                  __nv_bfloat16* __restrict__ lo, int M, int Kin)
{
    int idx = blockIdx.x * blockDim.x + threadIdx.x;   // over M * KP/4
    if (idx >= M * (KP / 4)) return;
    int r  = idx / (KP / 4);
    int c  = (idx - r * (KP / 4)) * 4;
    float4 v = make_float4(0.f, 0.f, 0.f, 0.f);
    if (c + 3 < Kin) v = *(const float4*)(in + (size_t)r * Kin + c);
    uint2 pl;
    uint2 ph = split_pack4(v, &pl);
    *(uint2*)(hi + (size_t)r * KP + c) = ph;
    *(uint2*)(lo + (size_t)r * KP + c) = pl;
}

// ============================================================================
// weight[l] is [K=1000][N=1000] (N contiguous); emit transposed split
// ============================================================================
__global__ __launch_bounds__(256)
void convT_split_k(const float* __restrict__ w, __nv_bfloat16* __restrict__ hi,
                   __nv_bfloat16* __restrict__ lo)
{
    int idx = blockIdx.x * blockDim.x + threadIdx.x;   // over DD * KP/4
    if (idx >= DD * (KP / 4)) return;
    int n = idx / (KP / 4);
    int k = (idx - n * (KP / 4)) * 4;
    float4 v = make_float4(0.f, 0.f, 0.f, 0.f);
    if (k + 3 < DD) {
        v.x = w[(size_t)(k    ) * DD + n];
        v.y = w[(size_t)(k + 1) * DD + n];
        v.z = w[(size_t)(k + 2) * DD + n];
        v.w = w[(size_t)(k + 3) * DD + n];
    }
    uint2 pl;
    uint2 ph = split_pack4(v, &pl);
    *(uint2*)(hi + (size_t)n * KP + k) = ph;
    *(uint2*)(lo + (size_t)n * KP + k) = pl;
}

// ============================================================================
// CSR build (per launch; deterministic edge list)
// ============================================================================
__global__ void zero_deg_k(int* __restrict__ deg)
{
    int i = blockIdx.x * blockDim.x + threadIdx.x;
    if (i < NN) deg[i] = 0;
}
__global__ void hist_k(const int* __restrict__ dst, int* __restrict__ deg)
{
    int e = blockIdx.x * blockDim.x + threadIdx.x;
    if (e < EE) atomicAdd(&deg[dst[e]], 1);
}
__global__ __launch_bounds__(1024)
void scan_k(const int* __restrict__ deg, int* __restrict__ off,
            int* __restrict__ cur)
{
    __shared__ int part[1024];
    const int tid = threadIdx.x;
    const int per = DIVUP(NN, 1024);     // 20
    const int base = tid * per;
    int loc[DIVUP(NN, 1024)];
    int s = 0;
#pragma unroll
    for (int i = 0; i < per; ++i) {
        int idx = base + i;
        int v = (idx < NN) ? deg[idx] : 0;
        loc[i] = v;
        s += v;
    }
    part[tid] = s;
    __syncthreads();
    for (int d = 1; d < 1024; d <<= 1) {
        int v = (tid >= d) ? part[tid - d] : 0;
        __syncthreads();
        part[tid] += v;
        __syncthreads();
    }
    int run = part[tid] - s;
#pragma unroll
    for (int i = 0; i < per; ++i) {
        int idx = base + i;
        if (idx < NN) { off[idx] = run; cur[idx] = run; run += loc[i]; }
    }
    if (tid == 1023) off[NN] = run;
}
__global__ void fill_k(const int* __restrict__ dst, int* __restrict__ cur,
                       int* __restrict__ eid)
{
    int e = blockIdx.x * blockDim.x + threadIdx.x;
    if (e < EE) {
        int p = atomicAdd(&cur[dst[e]], 1);
        eid[p] = e;
    }
}

// ============================================================================
// CSR scatter: block per dst node; emits bf16 hi/lo split of agg directly
// ============================================================================
__global__ __launch_bounds__(256)
void scatter_csr_k(const float* __restrict__ m, const int* __restrict__ src,
                   const float* __restrict__ ew, const int* __restrict__ off,
                   const int* __restrict__ eid,
                   __nv_bfloat16* __restrict__ ahi, __nv_bfloat16* __restrict__ alo)
{
    const int n = blockIdx.x;
    const int t = threadIdx.x;
    if (t >= D4) return;
    const int s0 = off[n];
    const int s1 = off[n + 1];
    float4 acc = make_float4(0.f, 0.f, 0.f, 0.f);
    for (int i = s0; i < s1; ++i) {
        const int e = eid[i];
        const int s = src[e];
        const float w = ew[e];
        const float4 v = *(const float4*)(m + (size_t)s * DD + t * 4);
        acc.x += v.x * w;
        acc.y += v.y * w;
        acc.z += v.z * w;
        acc.w += v.w * w;
    }
    uint2 pl;
    uint2 ph = split_pack4(acc, &pl);
    *(uint2*)(ahi + (size_t)n * KP + t * 4) = ph;
    *(uint2*)(alo + (size_t)n * KP + t * 4) = pl;
}

// ============================================================================
// mma.sync GEMM: C[M,Nn] = Ahi@Bhi^T + Ahi@Blo^T + Alo@Bhi^T (+ bias)
// A: [M][KP] bf16 K-major; B: [Nn][KP] bf16 K-major. fp32 register accum.
// CTA tile 128x128, K chunk 32, 2-stage cp.async pipeline, 2 CTAs/SM.
// ldmatrix.x4 fragment loads; SMEM row stride 80 B (conflict-free: word
// offsets 20*r mod 32 distinct for r=0..7).
// Pass order reuses frag regs to stay under 128 regs @ 512 thr/SM:
//   b_hi, a_hi -> hi*hi ; a_lo -> lo*hi ; b_lo, a_hi(reload) -> hi*lo
// ============================================================================
#define ASTRIDE 80
#define TILE_SB (128 * ASTRIDE)   // 10240 B
#define STAGE_SB (4 * TILE_SB)    // 40960 B
#define SMEM_DYN (2 * STAGE_SB)   // 81920 B

template<bool BIAS>
__global__ __launch_bounds__(256, 2)
void mma_gemm_k(const __nv_bfloat16* __restrict__ Ahi, const __nv_bfloat16* __restrict__ Alo,
                const __nv_bfloat16* __restrict__ Bhi, const __nv_bfloat16* __restrict__ Blo,
                const float* __restrict__ bias, float* __restrict__ C,
                int M, int Nn)
{
    extern __shared__ char smem[];
    const int tid  = threadIdx.x;
    const int lane = tid & 31;
    const int wid  = tid >> 5;
    const int gr   = lane >> 2;
    const int gc   = lane & 3;
    const int wm   = wid >> 2;      // 0..1 (64-row half)
    const int wn   = wid & 3;       // 0..3 (32-col quarter)
    const int row0 = blockIdx.y * 128;
    const int col0 = blockIdx.x * 128;

    const uint4* pAhi = (const uint4*)Ahi;
    const uint4* pAlo = (const uint4*)Alo;
    const uint4* pBhi = (const uint4*)Bhi;
    const uint4* pBlo = (const uint4*)Blo;

    const uint32_t sbase = smem_u32(smem);

    float acc[4][4][4];
#pragma unroll
    for (int i = 0; i < 4; i++)
#pragma unroll
        for (int j = 0; j < 4; j++)
#pragma unroll
            for (int k = 0; k < 4; k++) acc[i][j][k] = 0.f;

    // ldmatrix per-lane base offsets within a tile
    const int g8 = lane >> 3;       // matrix index 0..3
    const int r8 = lane & 7;        // row within 8x8
    // A: matrices (m0-7,k0-7),(m8-15,k0-7),(m0-7,k8-15),(m8-15,k8-15)
    const uint32_t aoff = (uint32_t)((wm * 64 + (g8 & 1) * 8 + r8) * ASTRIDE
                                     + (g8 >> 1) * 16);
    // B: matrices (n0-7,k0-7),(n0-7,k8-15),(n8-15,k0-7),(n8-15,k8-15)
    const uint32_t boff = (uint32_t)((wn * 32 + (g8 >> 1) * 8 + r8) * ASTRIDE
                                     + (g8 & 1) * 16);

    // cp.async mapping: 512 slots per tile, thread covers s = tid, tid+256
    auto load_chunk = [&](int c, int stage) {
        const uint32_t st = sbase + stage * STAGE_SB;
        const int k0u = c * 4;   // uint4 offset within padded row (32 bf16)
#pragma unroll
        for (int half = 0; half < 2; ++half) {
            const int s = tid + half * 256;
            const int row = s >> 2;
            const int u = s & 3;
            const uint32_t soff = (uint32_t)(row * ASTRIDE + u * 16);
            const int ar = row0 + row;
            const uint32_t asz = (ar < M) ? 16u : 0u;
            const size_t ga = (size_t)((ar < M) ? ar : 0) * KP8 + (k0u + u);
            cp16(st + 0 * TILE_SB + soff, pAhi + ga, asz);
            cp16(st + 1 * TILE_SB + soff, pAlo + ga, asz);
            const int br = col0 + row;
            const uint32_t bsz = (br < Nn) ? 16u : 0u;
            const size_t gb = (size_t)((br < Nn) ? br : 0) * KP8 + (k0u + u);
            cp16(st + 2 * TILE_SB + soff, pBhi + gb, bsz);
            cp16(st + 3 * TILE_SB + soff, pBlo + gb, bsz);
        }
        CP_COMMIT();
    };

    load_chunk(0, 0);

    for (int c = 0; c < NCHUNK2; ++c) {
        if (c + 1 < NCHUNK2) {
            load_chunk(c + 1, (c + 1) & 1);
            CP_WAIT1();
        } else {
            CP_WAIT0();
        }
        __syncthreads();

        const uint32_t st = sbase + (c & 1) * STAGE_SB;
        const uint32_t sAh = st + 0 * TILE_SB + aoff;
        const uint32_t sAl = st + 1 * TILE_SB + aoff;
        const uint32_t sBh = st + 2 * TILE_SB + boff;
        const uint32_t sBl = st + 3 * TILE_SB + boff;

#pragma unroll
        for (int ks = 0; ks < 2; ++ks) {
            const uint32_t ko = ks * 32;
            uint32_t a[4][4];
            uint32_t b[8];

            // b_hi (p=0 -> nt 0,1 ; p=1 -> nt 2,3)
            ldsm4(b + 0, sBh + ko);
            ldsm4(b + 4, sBh + ko + 16 * ASTRIDE);
            // a_hi
#pragma unroll
            for (int mt = 0; mt < 4; ++mt)
                ldsm4(a[mt], sAh + ko + mt * 16 * ASTRIDE);
            // hi*hi
#pragma unroll
            for (int mt = 0; mt < 4; ++mt)
#pragma unroll
                for (int nt = 0; nt < 4; ++nt)
                    mma16816(acc[mt][nt], a[mt], b + (nt >> 1) * 4 + (nt & 1) * 2);
            // a_lo (overwrite a)
#pragma unroll
            for (int mt = 0; mt < 4; ++mt)
                ldsm4(a[mt], sAl + ko + mt * 16 * ASTRIDE);
            // lo*hi
#pragma unroll
            for (int mt = 0; mt < 4; ++mt)
#pragma unroll
                for (int nt = 0; nt < 4; ++nt)
                    mma16816(acc[mt][nt], a[mt], b + (nt >> 1) * 4 + (nt & 1) * 2);
            // b_lo (overwrite b)
            ldsm4(b + 0, sBl + ko);
            ldsm4(b + 4, sBl + ko + 16 * ASTRIDE);
            // a_hi reload
#pragma unroll
            for (int mt = 0; mt < 4; ++mt)
                ldsm4(a[mt], sAh + ko + mt * 16 * ASTRIDE);
            // hi*lo
#pragma unroll
            for (int mt = 0; mt < 4; ++mt)
#pragma unroll
                for (int nt = 0; nt < 4; ++nt)
                    mma16816(acc[mt][nt], a[mt], b + (nt >> 1) * 4 + (nt & 1) * 2);
        }
        __syncthreads();
    }

    // ---- epilogue: d0,d1 -> (gr, 2gc..+1); d2,d3 -> (gr+8, 2gc..+1) ----
#pragma unroll
    for (int mt = 0; mt < 4; ++mt) {
        const int r1 = row0 + wm * 64 + mt * 16 + gr;
        const int r2 = r1 + 8;
#pragma unroll
        for (int nt = 0; nt < 4; ++nt) {
            const int cc = col0 + wn * 32 + nt * 8 + 2 * gc;
            if (cc < Nn) {
                float bx = 0.f, by = 0.f;
                if (BIAS) { bx = bias[cc]; by = bias[cc + 1]; }
                if (r1 < M) {
                    float2 v = make_float2(acc[mt][nt][0] + bx, acc[mt][nt][1] + by);
                    *(float2*)&C[(size_t)r1 * Nn + cc] = v;
                }
                if (r2 < M) {
                    float2 v = make_float2(acc[mt][nt][2] + bx, acc[mt][nt][3] + by);
                    *(float2*)&C[(size_t)r2 * Nn + cc] = v;
                }
            }
        }
    }
}

// ============================================================================
// GRU elementwise, fused with bf16 hi/lo split of the new h
// ============================================================================
__device__ __forceinline__ float gru1(float ir, float iz, float inn,
                                      float hr, float hz, float hn, float h)
{
    float r = 1.f / (1.f + expf(-(ir + hr)));
    float z = 1.f / (1.f + expf(-(iz + hz)));
    float n = tanhf(inn + r * hn);
    return (1.f - z) * n + z * h;
}

__global__ __launch_bounds__(256)
void gru_split_k(const float4* __restrict__ gi, const float4* __restrict__ gh,
                 const float4* __restrict__ hin, float4* __restrict__ hout,
                 __nv_bfloat16* __restrict__ hhi, __nv_bfloat16* __restrict__ hlo)
{
    int idx = blockIdx.x * blockDim.x + threadIdx.x;
    if (idx >= NN * D4) return;
    int n  = idx / D4;
    int dv = idx - n * D4;
    size_t b3 = (size_t)n * (3 * D4);
    float4 ir = gi[b3 + dv];
    float4 iz = gi[b3 + D4 + dv];
    float4 in_ = gi[b3 + 2 * D4 + dv];
    float4 hr = gh[b3 + dv];
    float4 hz = gh[b3 + D4 + dv];
    float4 hn = gh[b3 + 2 * D4 + dv];
    float4 h = hin[(size_t)n * D4 + dv];
    float4 o;
    o.x = gru1(ir.x, iz.x, in_.x, hr.x, hz.x, hn.x, h.x);
    o.y = gru1(ir.y, iz.y, in_.y, hr.y, hz.y, hn.y, h.y);
    o.z = gru1(ir.z, iz.z, in_.z, hr.z, hz.z, hn.z, h.z);
    o.w = gru1(ir.w, iz.w, in_.w, hr.w, hz.w, hn.w, h.w);
    hout[(size_t)n * D4 + dv] = o;
    uint2 pl;
    uint2 ph = split_pack4(o, &pl);
    *(uint2*)(hhi + (size_t)n * KP + dv * 4) = ph;
    *(uint2*)(hlo + (size_t)n * KP + dv * 4) = pl;
}

// ============================================================================
// Final: out[n] = sum_d relu(h[n,d]) * fc_w[d] + fc_b   (warp per node)
// ============================================================================
__global__ __launch_bounds__(256)
void fc_k(const float* __restrict__ h, const float* __restrict__ fw,
          const float* __restrict__ fb, float* __restrict__ out)
{
    int warp = (blockIdx.x * 256 + threadIdx.x) >> 5;
    int lane = threadIdx.x & 31;
    if (warp >= NN) return;
    const float4* h4 = (const float4*)(h + (size_t)warp * DD);
    const float4* w4 = (const float4*)fw;
    float s = 0.f;
    for (int i = lane; i < D4; i += 32) {
        float4 hv = h4[i];
        float4 wv = w4[i];
        s += fmaxf(hv.x, 0.f) * wv.x + fmaxf(hv.y, 0.f) * wv.y +
             fmaxf(hv.z, 0.f) * wv.z + fmaxf(hv.w, 0.f) * wv.w;
    }
#pragma unroll
    for (int off = 16; off; off >>= 1)
        s += __shfl_down_sync(0xffffffffu, s, off);
    if (lane == 0) out[warp] = s + fb[0];
}

// ============================================================================
// launch
// ============================================================================
extern "C" void kernel_launch(void* const* d_in, const int* in_sizes, int n_in,
                              void* d_out, int out_size)
{
    const float* x      = (const float*)d_in[0];
    const int*   ei     = (const int*)  d_in[1];
    const float* ew     = (const float*)d_in[2];
    const float* weight = (const float*)d_in[3];
    const float* w_ih   = (const float*)d_in[4];
    const float* w_hh   = (const float*)d_in[5];
    const float* b_ih   = (const float*)d_in[6];
    const float* b_hh   = (const float*)d_in[7];
    const float* fc_w   = (const float*)d_in[8];
    const float* fc_b   = (const float*)d_in[9];
    float* out = (float*)d_out;

    float *pm, *pgi, *pgh, *ph;
    __nv_bfloat16 *pa_hi, *pa_lo, *ph_hi, *ph_lo;
    __nv_bfloat16 *pwih_hi, *pwih_lo, *pwhh_hi, *pwhh_lo, *pwt_hi, *pwt_lo;
    int *pdeg, *poff, *pcur, *peid;
    cudaGetSymbolAddress((void**)&pm,     g_m);
    cudaGetSymbolAddress((void**)&pgi,    g_gi);
    cudaGetSymbolAddress((void**)&pgh,    g_gh);
    cudaGetSymbolAddress((void**)&ph,     g_h);
    cudaGetSymbolAddress((void**)&pa_hi,  g_a_hi);
    cudaGetSymbolAddress((void**)&pa_lo,  g_a_lo);
    cudaGetSymbolAddress((void**)&ph_hi,  g_h_hi);
    cudaGetSymbolAddress((void**)&ph_lo,  g_h_lo);
    cudaGetSymbolAddress((void**)&pwih_hi, g_wih_hi);
    cudaGetSymbolAddress((void**)&pwih_lo, g_wih_lo);
    cudaGetSymbolAddress((void**)&pwhh_hi, g_whh_hi);
    cudaGetSymbolAddress((void**)&pwhh_lo, g_whh_lo);
    cudaGetSymbolAddress((void**)&pwt_hi,  g_wt_hi);
    cudaGetSymbolAddress((void**)&pwt_lo,  g_wt_lo);
    cudaGetSymbolAddress((void**)&pdeg,   g_deg);
    cudaGetSymbolAddress((void**)&poff,   g_off);
    cudaGetSymbolAddress((void**)&pcur,   g_cur);
    cudaGetSymbolAddress((void**)&peid,   g_eid);

    const int* src = ei;
    const int* dst = ei + EE;

    cudaFuncSetAttribute(mma_gemm_k<false>,
                         cudaFuncAttributeMaxDynamicSharedMemorySize, SMEM_DYN);
    cudaFuncSetAttribute(mma_gemm_k<true>,
                         cudaFuncAttributeMaxDynamicSharedMemorySize, SMEM_DYN);

    // ---- CSR build (edges fixed across layers) ----
    zero_deg_k<<<DIVUP(NN, 256), 256>>>(pdeg);
    hist_k<<<DIVUP(EE, 256), 256>>>(dst, pdeg);
    scan_k<<<1, 1024>>>(pdeg, poff, pcur);
    fill_k<<<DIVUP(EE, 256), 256>>>(dst, pcur, peid);

    // ---- weight conversions ----
    conv_split_k<<<DIVUP(TD * (KP / 4), 256), 256>>>(w_ih, pwih_hi, pwih_lo, TD, DD);
    conv_split_k<<<DIVUP(TD * (KP / 4), 256), 256>>>(w_hh, pwhh_hi, pwhh_lo, TD, DD);
    for (int l = 0; l < NLAYERS; ++l)
        convT_split_k<<<DIVUP(DD * (KP / 4), 256), 256>>>(
            weight + (size_t)l * DD * DD,
            pwt_hi + (size_t)l * DD * KP, pwt_lo + (size_t)l * DD * KP);

    // split x for layer 0 (later layers get the split from gru_split_k)
    conv_split_k<<<DIVUP(NN * (KP / 4), 256), 256>>>(x, ph_hi, ph_lo, NN, DD);

    dim3 grid1(DIVUP(DD, 128), DIVUP(NN, 128));   // 8 x 157
    dim3 grid3(DIVUP(TD, 128), DIVUP(NN, 128));   // 24 x 157
    const int ew_blocks = DIVUP(NN * D4, 256);

    for (int l = 0; l < NLAYERS; ++l) {
        const float* hin = (l == 0) ? x : ph;

        // m = h @ W[l]
        mma_gemm_k<false><<<grid1, 256, SMEM_DYN>>>(
            ph_hi, ph_lo,
            pwt_hi + (size_t)l * DD * KP, pwt_lo + (size_t)l * DD * KP,
            nullptr, pm, NN, DD);

        // agg = scatter_add(m[src] * ew, dst)  -> bf16 split directly
        scatter_csr_k<<<NN, 256>>>(pm, src, ew, poff, peid, pa_hi, pa_lo);

        // gi = agg @ w_ih^T + b_ih ; gh = h @ w_hh^T + b_hh
        mma_gemm_k<true><<<grid3, 256, SMEM_DYN>>>(
            pa_hi, pa_lo, pwih_hi, pwih_lo, b_ih, pgi, NN, TD);
        mma_gemm_k<true><<<grid3, 256, SMEM_DYN>>>(
            ph_hi, ph_lo, pwhh_hi, pwhh_lo, b_hh, pgh, NN, TD);

        // h = GRU(gi, gh, h), fused with split for next layer's GEMMs
        gru_split_k<<<ew_blocks, 256>>>((const float4*)pgi, (const float4*)pgh,
                                        (const float4*)hin, (float4*)ph,
                                        ph_hi, ph_lo);
    }

    // out = relu(h) @ fc_w^T + fc_b
    fc_k<<<DIVUP(NN, 8), 256>>>(ph, fc_w, fc_b, out);
}

// round 16
// speedup vs baseline: 2.8359x; 1.0032x over previous
#include <cuda_runtime.h>
#include <cuda_bf16.h>
#include <math.h>
#include <stdint.h>

// Problem constants (fixed by the reference)
#define NN 20000          // nodes
#define EE 160000         // edges
#define DD 1000           // feature dim
#define TD 3000           // 3*D
#define NLAYERS 3
#define D4 250            // D/4
#define KP 1024           // K padded to multiple of 64
#define KP8 (KP/8)        // uint4 (8 bf16) per padded row = 128
#define NCHUNK2 (KP/32)   // 32 chunks of K=32

#define DIVUP(a,b) (((a)+(b)-1)/(b))

// ---------------- scratch (device globals: sanctioned no-alloc path) --------
__device__ float g_m  [(size_t)NN * DD];   // 80 MB
__device__ float g_gi [(size_t)NN * TD];   // 240 MB
__device__ float g_gh [(size_t)NN * TD];   // 240 MB
__device__ float g_h  [(size_t)NN * DD];   // 80 MB
// bf16 hi/lo split operand buffers (K padded to KP; pad cols stay zero from
// static zero-initialization — kernels only ever write cols [0, DD))
__device__ __nv_bfloat16 g_a_hi [(size_t)NN * KP];
__device__ __nv_bfloat16 g_a_lo [(size_t)NN * KP];
__device__ __nv_bfloat16 g_h_hi [(size_t)NN * KP];
__device__ __nv_bfloat16 g_h_lo [(size_t)NN * KP];
__device__ __nv_bfloat16 g_wih_hi[(size_t)TD * KP];
__device__ __nv_bfloat16 g_wih_lo[(size_t)TD * KP];
__device__ __nv_bfloat16 g_whh_hi[(size_t)TD * KP];
__device__ __nv_bfloat16 g_whh_lo[(size_t)TD * KP];
__device__ __nv_bfloat16 g_wt_hi [(size_t)NLAYERS * DD * KP];
__device__ __nv_bfloat16 g_wt_lo [(size_t)NLAYERS * DD * KP];
// CSR of edge list keyed by dst (rebuilt every launch; deterministic inputs)
__device__ int g_deg[NN];
__device__ int g_off[NN + 1];
__device__ int g_cur[NN];
__device__ int g_eid[EE];

// ====================== helpers (sm_80-baseline PTX only) ===================
__device__ __forceinline__ uint32_t smem_u32(const void* p) {
    uint32_t a;
    asm("{ .reg .u64 t; cvta.to.shared.u64 t, %1; cvt.u32.u64 %0, t; }"
        : "=r"(a) : "l"(p));
    return a;
}
__device__ __forceinline__ void cp16(uint32_t s, const void* g, uint32_t sz) {
    asm volatile("cp.async.cg.shared.global [%0], [%1], 16, %2;"
                 :: "r"(s), "l"(g), "r"(sz) : "memory");
}
#define CP_COMMIT() asm volatile("cp.async.commit_group;" ::: "memory")
#define CP_WAIT1()  asm volatile("cp.async.wait_group 1;" ::: "memory")
#define CP_WAIT0()  asm volatile("cp.async.wait_group 0;" ::: "memory")

// D += A(16x16 bf16, row) @ B(16x8 bf16, col)
__device__ __forceinline__ void mma16816(float* d, const uint32_t* a, const uint32_t* b) {
    asm volatile(
        "mma.sync.aligned.m16n8k16.row.col.f32.bf16.bf16.f32 "
        "{%0,%1,%2,%3}, {%4,%5,%6,%7}, {%8,%9}, {%0,%1,%2,%3};"
        : "+f"(d[0]), "+f"(d[1]), "+f"(d[2]), "+f"(d[3])
        : "r"(a[0]), "r"(a[1]), "r"(a[2]), "r"(a[3]), "r"(b[0]), "r"(b[1]));
}
// ldmatrix x4: four 8x8 b16 tiles, one address per lane
__device__ __forceinline__ void ldsm4(uint32_t* r, uint32_t addr) {
    asm volatile("ldmatrix.sync.aligned.m8n8.x4.shared.b16 {%0,%1,%2,%3}, [%4];"
        : "=r"(r[0]), "=r"(r[1]), "=r"(r[2]), "=r"(r[3]) : "r"(addr));
}

__device__ __forceinline__ uint2 split_pack4(float4 v, uint2* lo_out) {
    __nv_bfloat16 h0 = __float2bfloat16(v.x), h1 = __float2bfloat16(v.y);
    __nv_bfloat16 h2 = __float2bfloat16(v.z), h3 = __float2bfloat16(v.w);
    __nv_bfloat16 l0 = __float2bfloat16(v.x - __bfloat162float(h0));
    __nv_bfloat16 l1 = __float2bfloat16(v.y - __bfloat162float(h1));
    __nv_bfloat16 l2 = __float2bfloat16(v.z - __bfloat162float(h2));
    __nv_bfloat16 l3 = __float2bfloat16(v.w - __bfloat162float(h3));
    uint2 ph, pl;
    ph.x = ((uint32_t)__bfloat16_as_ushort(h1) << 16) | __bfloat16_as_ushort(h0);
    ph.y = ((uint32_t)__bfloat16_as_ushort(h3) << 16) | __bfloat16_as_ushort(h2);
    pl.x = ((uint32_t)__bfloat16_as_ushort(l1) << 16) | __bfloat16_as_ushort(l0);
    pl.y = ((uint32_t)__bfloat16_as_ushort(l3) << 16) | __bfloat16_as_ushort(l2);
    *lo_out = pl;
    return ph;
}

// ============================================================================
// fp32 -> bf16 hi/lo split, row-major [M][Kin] -> [M][KP] (tail zero)
// ============================================================================
__global__ __launch_bounds__(256)
void conv_split_k(const float* __restrict__ in, __nv_bfloat16* __restrict__ hi,
                  __nv_bfloat16* __restrict__ lo, int M, int Kin)
{
    int idx = blockIdx.x * blockDim.x + threadIdx.x;   // over M * KP/4
    if (idx >= M * (KP / 4)) return;
    int r  = idx / (KP / 4);
    int c  = (idx - r * (KP / 4)) * 4;
    float4 v = make_float4(0.f, 0.f, 0.f, 0.f);
    if (c + 3 < Kin) v = *(const float4*)(in + (size_t)r * Kin + c);
    uint2 pl;
    uint2 ph = split_pack4(v, &pl);
    *(uint2*)(hi + (size_t)r * KP + c) = ph;
    *(uint2*)(lo + (size_t)r * KP + c) = pl;
}

// ============================================================================
// weight[l] is [K=1000][N=1000] (N contiguous); emit transposed split
// ============================================================================
__global__ __launch_bounds__(256)
void convT_split_k(const float* __restrict__ w, __nv_bfloat16* __restrict__ hi,
                   __nv_bfloat16* __restrict__ lo)
{
    int idx = blockIdx.x * blockDim.x + threadIdx.x;   // over DD * KP/4
    if (idx >= DD * (KP / 4)) return;
    int n = idx / (KP / 4);
    int k = (idx - n * (KP / 4)) * 4;
    float4 v = make_float4(0.f, 0.f, 0.f, 0.f);
    if (k + 3 < DD) {
        v.x = w[(size_t)(k    ) * DD + n];
        v.y = w[(size_t)(k + 1) * DD + n];
        v.z = w[(size_t)(k + 2) * DD + n];
        v.w = w[(size_t)(k + 3) * DD + n];
    }
    uint2 pl;
    uint2 ph = split_pack4(v, &pl);
    *(uint2*)(hi + (size_t)n * KP + k) = ph;
    *(uint2*)(lo + (size_t)n * KP + k) = pl;
}

// ============================================================================
// CSR build (per launch; deterministic edge list)
// ============================================================================
__global__ void zero_deg_k(int* __restrict__ deg)
{
    int i = blockIdx.x * blockDim.x + threadIdx.x;
    if (i < NN) deg[i] = 0;
}
__global__ void hist_k(const int* __restrict__ dst, int* __restrict__ deg)
{
    int e = blockIdx.x * blockDim.x + threadIdx.x;
    if (e < EE) atomicAdd(&deg[dst[e]], 1);
}
__global__ __launch_bounds__(1024)
void scan_k(const int* __restrict__ deg, int* __restrict__ off,
            int* __restrict__ cur)
{
    __shared__ int part[1024];
    const int tid = threadIdx.x;
    const int per = DIVUP(NN, 1024);     // 20
    const int base = tid * per;
    int loc[DIVUP(NN, 1024)];
    int s = 0;
#pragma unroll
    for (int i = 0; i < per; ++i) {
        int idx = base + i;
        int v = (idx < NN) ? deg[idx] : 0;
        loc[i] = v;
        s += v;
    }
    part[tid] = s;
    __syncthreads();
    for (int d = 1; d < 1024; d <<= 1) {
        int v = (tid >= d) ? part[tid - d] : 0;
        __syncthreads();
        part[tid] += v;
        __syncthreads();
    }
    int run = part[tid] - s;
#pragma unroll
    for (int i = 0; i < per; ++i) {
        int idx = base + i;
        if (idx < NN) { off[idx] = run; cur[idx] = run; run += loc[i]; }
    }
    if (tid == 1023) off[NN] = run;
}
__global__ void fill_k(const int* __restrict__ dst, int* __restrict__ cur,
                       int* __restrict__ eid)
{
    int e = blockIdx.x * blockDim.x + threadIdx.x;
    if (e < EE) {
        int p = atomicAdd(&cur[dst[e]], 1);
        eid[p] = e;
    }
}

// ============================================================================
// CSR scatter: block per dst node; emits bf16 hi/lo split of agg directly
// ============================================================================
__global__ __launch_bounds__(256)
void scatter_csr_k(const float* __restrict__ m, const int* __restrict__ src,
                   const float* __restrict__ ew, const int* __restrict__ off,
                   const int* __restrict__ eid,
                   __nv_bfloat16* __restrict__ ahi, __nv_bfloat16* __restrict__ alo)
{
    const int n = blockIdx.x;
    const int t = threadIdx.x;
    if (t >= D4) return;
    const int s0 = off[n];
    const int s1 = off[n + 1];
    float4 acc = make_float4(0.f, 0.f, 0.f, 0.f);
    for (int i = s0; i < s1; ++i) {
        const int e = eid[i];
        const int s = src[e];
        const float w = ew[e];
        const float4 v = *(const float4*)(m + (size_t)s * DD + t * 4);
        acc.x += v.x * w;
        acc.y += v.y * w;
        acc.z += v.z * w;
        acc.w += v.w * w;
    }
    uint2 pl;
    uint2 ph = split_pack4(acc, &pl);
    *(uint2*)(ahi + (size_t)n * KP + t * 4) = ph;
    *(uint2*)(alo + (size_t)n * KP + t * 4) = pl;
}

// ============================================================================
// mma.sync GEMM: C[M,Nn] = Ahi@Bhi^T + Ahi@Blo^T + Alo@Bhi^T (+ bias)
// A: [M][KP] bf16 K-major; B: [Nn][KP] bf16 K-major. fp32 register accum.
// CTA tile 128x128, K chunk 32, 2-stage cp.async pipeline, 2 CTAs/SM.
// ldmatrix.x4 fragment loads; SMEM row stride 80 B (conflict-free).
// Pass order keeps b_hi AND b_lo live (16 b-regs) so a_hi is loaded once:
//   b_hi, b_lo, a_hi -> hi*hi, hi*lo ; a_lo -> lo*hi
// 12 ldsm4 per k16-step (was 16), no reloads. ~112 regs.
// ============================================================================
#define ASTRIDE 80
#define TILE_SB (128 * ASTRIDE)   // 10240 B
#define STAGE_SB (4 * TILE_SB)    // 40960 B
#define SMEM_DYN (2 * STAGE_SB)   // 81920 B

template<bool BIAS>
__global__ __launch_bounds__(256, 2)
void mma_gemm_k(const __nv_bfloat16* __restrict__ Ahi, const __nv_bfloat16* __restrict__ Alo,
                const __nv_bfloat16* __restrict__ Bhi, const __nv_bfloat16* __restrict__ Blo,
                const float* __restrict__ bias, float* __restrict__ C,
                int M, int Nn)
{
    extern __shared__ char smem[];
    const int tid  = threadIdx.x;
    const int lane = tid & 31;
    const int wid  = tid >> 5;
    const int gr   = lane >> 2;
    const int gc   = lane & 3;
    const int wm   = wid >> 2;      // 0..1 (64-row half)
    const int wn   = wid & 3;       // 0..3 (32-col quarter)
    const int row0 = blockIdx.y * 128;
    const int col0 = blockIdx.x * 128;

    const uint4* pAhi = (const uint4*)Ahi;
    const uint4* pAlo = (const uint4*)Alo;
    const uint4* pBhi = (const uint4*)Bhi;
    const uint4* pBlo = (const uint4*)Blo;

    const uint32_t sbase = smem_u32(smem);

    float acc[4][4][4];
#pragma unroll
    for (int i = 0; i < 4; i++)
#pragma unroll
        for (int j = 0; j < 4; j++)
#pragma unroll
            for (int k = 0; k < 4; k++) acc[i][j][k] = 0.f;

    // ldmatrix per-lane base offsets within a tile
    const int g8 = lane >> 3;       // matrix index 0..3
    const int r8 = lane & 7;        // row within 8x8
    // A: matrices (m0-7,k0-7),(m8-15,k0-7),(m0-7,k8-15),(m8-15,k8-15)
    const uint32_t aoff = (uint32_t)((wm * 64 + (g8 & 1) * 8 + r8) * ASTRIDE
                                     + (g8 >> 1) * 16);
    // B: matrices (n0-7,k0-7),(n0-7,k8-15),(n8-15,k0-7),(n8-15,k8-15)
    const uint32_t boff = (uint32_t)((wn * 32 + (g8 >> 1) * 8 + r8) * ASTRIDE
                                     + (g8 & 1) * 16);

    // cp.async mapping: 512 slots per tile, thread covers s = tid, tid+256
    auto load_chunk = [&](int c, int stage) {
        const uint32_t st = sbase + stage * STAGE_SB;
        const int k0u = c * 4;   // uint4 offset within padded row (32 bf16)
#pragma unroll
        for (int half = 0; half < 2; ++half) {
            const int s = tid + half * 256;
            const int row = s >> 2;
            const int u = s & 3;
            const uint32_t soff = (uint32_t)(row * ASTRIDE + u * 16);
            const int ar = row0 + row;
            const uint32_t asz = (ar < M) ? 16u : 0u;
            const size_t ga = (size_t)((ar < M) ? ar : 0) * KP8 + (k0u + u);
            cp16(st + 0 * TILE_SB + soff, pAhi + ga, asz);
            cp16(st + 1 * TILE_SB + soff, pAlo + ga, asz);
            const int br = col0 + row;
            const uint32_t bsz = (br < Nn) ? 16u : 0u;
            const size_t gb = (size_t)((br < Nn) ? br : 0) * KP8 + (k0u + u);
            cp16(st + 2 * TILE_SB + soff, pBhi + gb, bsz);
            cp16(st + 3 * TILE_SB + soff, pBlo + gb, bsz);
        }
        CP_COMMIT();
    };

    load_chunk(0, 0);

    for (int c = 0; c < NCHUNK2; ++c) {
        if (c + 1 < NCHUNK2) {
            load_chunk(c + 1, (c + 1) & 1);
            CP_WAIT1();
        } else {
            CP_WAIT0();
        }
        __syncthreads();

        const uint32_t st = sbase + (c & 1) * STAGE_SB;
        const uint32_t sAh = st + 0 * TILE_SB + aoff;
        const uint32_t sAl = st + 1 * TILE_SB + aoff;
        const uint32_t sBh = st + 2 * TILE_SB + boff;
        const uint32_t sBl = st + 3 * TILE_SB + boff;

#pragma unroll
        for (int ks = 0; ks < 2; ++ks) {
            const uint32_t ko = ks * 32;
            uint32_t a[4][4];
            uint32_t b[2][8];

            // both B operands live (p=0 -> nt 0,1 ; p=1 -> nt 2,3)
            ldsm4(b[0] + 0, sBh + ko);
            ldsm4(b[0] + 4, sBh + ko + 16 * ASTRIDE);
            ldsm4(b[1] + 0, sBl + ko);
            ldsm4(b[1] + 4, sBl + ko + 16 * ASTRIDE);
            // a_hi (single load)
#pragma unroll
            for (int mt = 0; mt < 4; ++mt)
                ldsm4(a[mt], sAh + ko + mt * 16 * ASTRIDE);
            // hi*hi
#pragma unroll
            for (int mt = 0; mt < 4; ++mt)
#pragma unroll
                for (int nt = 0; nt < 4; ++nt)
                    mma16816(acc[mt][nt], a[mt], b[0] + (nt >> 1) * 4 + (nt & 1) * 2);
            // hi*lo
#pragma unroll
            for (int mt = 0; mt < 4; ++mt)
#pragma unroll
                for (int nt = 0; nt < 4; ++nt)
                    mma16816(acc[mt][nt], a[mt], b[1] + (nt >> 1) * 4 + (nt & 1) * 2);
            // a_lo (overwrite a)
#pragma unroll
            for (int mt = 0; mt < 4; ++mt)
                ldsm4(a[mt], sAl + ko + mt * 16 * ASTRIDE);
            // lo*hi
#pragma unroll
            for (int mt = 0; mt < 4; ++mt)
#pragma unroll
                for (int nt = 0; nt < 4; ++nt)
                    mma16816(acc[mt][nt], a[mt], b[0] + (nt >> 1) * 4 + (nt & 1) * 2);
        }
        __syncthreads();
    }

    // ---- epilogue: d0,d1 -> (gr, 2gc..+1); d2,d3 -> (gr+8, 2gc..+1) ----
#pragma unroll
    for (int mt = 0; mt < 4; ++mt) {
        const int r1 = row0 + wm * 64 + mt * 16 + gr;
        const int r2 = r1 + 8;
#pragma unroll
        for (int nt = 0; nt < 4; ++nt) {
            const int cc = col0 + wn * 32 + nt * 8 + 2 * gc;
            if (cc < Nn) {
                float bx = 0.f, by = 0.f;
                if (BIAS) { bx = bias[cc]; by = bias[cc + 1]; }
                if (r1 < M) {
                    float2 v = make_float2(acc[mt][nt][0] + bx, acc[mt][nt][1] + by);
                    *(float2*)&C[(size_t)r1 * Nn + cc] = v;
                }
                if (r2 < M) {
                    float2 v = make_float2(acc[mt][nt][2] + bx, acc[mt][nt][3] + by);
                    *(float2*)&C[(size_t)r2 * Nn + cc] = v;
                }
            }
        }
    }
}

// ============================================================================
// GRU elementwise, fused with bf16 hi/lo split of the new h
// ============================================================================
__device__ __forceinline__ float gru1(float ir, float iz, float inn,
                                      float hr, float hz, float hn, float h)
{
    float r = 1.f / (1.f + expf(-(ir + hr)));
    float z = 1.f / (1.f + expf(-(iz + hz)));
    float n = tanhf(inn + r * hn);
    return (1.f - z) * n + z * h;
}

__global__ __launch_bounds__(256)
void gru_split_k(const float4* __restrict__ gi, const float4* __restrict__ gh,
                 const float4* __restrict__ hin, float4* __restrict__ hout,
                 __nv_bfloat16* __restrict__ hhi, __nv_bfloat16* __restrict__ hlo)
{
    int idx = blockIdx.x * blockDim.x + threadIdx.x;
    if (idx >= NN * D4) return;
    int n  = idx / D4;
    int dv = idx - n * D4;
    size_t b3 = (size_t)n * (3 * D4);
    float4 ir = gi[b3 + dv];
    float4 iz = gi[b3 + D4 + dv];
    float4 in_ = gi[b3 + 2 * D4 + dv];
    float4 hr = gh[b3 + dv];
    float4 hz = gh[b3 + D4 + dv];
    float4 hn = gh[b3 + 2 * D4 + dv];
    float4 h = hin[(size_t)n * D4 + dv];
    float4 o;
    o.x = gru1(ir.x, iz.x, in_.x, hr.x, hz.x, hn.x, h.x);
    o.y = gru1(ir.y, iz.y, in_.y, hr.y, hz.y, hn.y, h.y);
    o.z = gru1(ir.z, iz.z, in_.z, hr.z, hz.z, hn.z, h.z);
    o.w = gru1(ir.w, iz.w, in_.w, hr.w, hz.w, hn.w, h.w);
    hout[(size_t)n * D4 + dv] = o;
    uint2 pl;
    uint2 ph = split_pack4(o, &pl);
    *(uint2*)(hhi + (size_t)n * KP + dv * 4) = ph;
    *(uint2*)(hlo + (size_t)n * KP + dv * 4) = pl;
}

// ============================================================================
// Final: out[n] = sum_d relu(h[n,d]) * fc_w[d] + fc_b   (warp per node)
// ============================================================================
__global__ __launch_bounds__(256)
void fc_k(const float* __restrict__ h, const float* __restrict__ fw,
          const float* __restrict__ fb, float* __restrict__ out)
{
    int warp = (blockIdx.x * 256 + threadIdx.x) >> 5;
    int lane = threadIdx.x & 31;
    if (warp >= NN) return;
    const float4* h4 = (const float4*)(h + (size_t)warp * DD);
    const float4* w4 = (const float4*)fw;
    float s = 0.f;
    for (int i = lane; i < D4; i += 32) {
        float4 hv = h4[i];
        float4 wv = w4[i];
        s += fmaxf(hv.x, 0.f) * wv.x + fmaxf(hv.y, 0.f) * wv.y +
             fmaxf(hv.z, 0.f) * wv.z + fmaxf(hv.w, 0.f) * wv.w;
    }
#pragma unroll
    for (int off = 16; off; off >>= 1)
        s += __shfl_down_sync(0xffffffffu, s, off);
    if (lane == 0) out[warp] = s + fb[0];
}

// ============================================================================
// launch  (ordered so ncu's "-s 5 -c 1" captures mma_gemm_k as launch #6)
// ============================================================================
extern "C" void kernel_launch(void* const* d_in, const int* in_sizes, int n_in,
                              void* d_out, int out_size)
{
    const float* x      = (const float*)d_in[0];
    const int*   ei     = (const int*)  d_in[1];
    const float* ew     = (const float*)d_in[2];
    const float* weight = (const float*)d_in[3];
    const float* w_ih   = (const float*)d_in[4];
    const float* w_hh   = (const float*)d_in[5];
    const float* b_ih   = (const float*)d_in[6];
    const float* b_hh   = (const float*)d_in[7];
    const float* fc_w   = (const float*)d_in[8];
    const float* fc_b   = (const float*)d_in[9];
    float* out = (float*)d_out;

    float *pm, *pgi, *pgh, *ph;
    __nv_bfloat16 *pa_hi, *pa_lo, *ph_hi, *ph_lo;
    __nv_bfloat16 *pwih_hi, *pwih_lo, *pwhh_hi, *pwhh_lo, *pwt_hi, *pwt_lo;
    int *pdeg, *poff, *pcur, *peid;
    cudaGetSymbolAddress((void**)&pm,     g_m);
    cudaGetSymbolAddress((void**)&pgi,    g_gi);
    cudaGetSymbolAddress((void**)&pgh,    g_gh);
    cudaGetSymbolAddress((void**)&ph,     g_h);
    cudaGetSymbolAddress((void**)&pa_hi,  g_a_hi);
    cudaGetSymbolAddress((void**)&pa_lo,  g_a_lo);
    cudaGetSymbolAddress((void**)&ph_hi,  g_h_hi);
    cudaGetSymbolAddress((void**)&ph_lo,  g_h_lo);
    cudaGetSymbolAddress((void**)&pwih_hi, g_wih_hi);
    cudaGetSymbolAddress((void**)&pwih_lo, g_wih_lo);
    cudaGetSymbolAddress((void**)&pwhh_hi, g_whh_hi);
    cudaGetSymbolAddress((void**)&pwhh_lo, g_whh_lo);
    cudaGetSymbolAddress((void**)&pwt_hi,  g_wt_hi);
    cudaGetSymbolAddress((void**)&pwt_lo,  g_wt_lo);
    cudaGetSymbolAddress((void**)&pdeg,   g_deg);
    cudaGetSymbolAddress((void**)&poff,   g_off);
    cudaGetSymbolAddress((void**)&pcur,   g_cur);
    cudaGetSymbolAddress((void**)&peid,   g_eid);

    const int* src = ei;
    const int* dst = ei + EE;

    cudaFuncSetAttribute(mma_gemm_k<false>,
                         cudaFuncAttributeMaxDynamicSharedMemorySize, SMEM_DYN);
    cudaFuncSetAttribute(mma_gemm_k<true>,
                         cudaFuncAttributeMaxDynamicSharedMemorySize, SMEM_DYN);

    dim3 grid1(DIVUP(DD, 128), DIVUP(NN, 128));   // 8 x 157
    dim3 grid3(DIVUP(TD, 128), DIVUP(NN, 128));   // 24 x 157
    const int ew_blocks = DIVUP(NN * D4, 256);

    // ---- prologue ordered so launch #6 is the m-GEMM (ncu -s 5 -c 1) ----
    // 1: split x (layer-0 activations)
    conv_split_k<<<DIVUP(NN * (KP / 4), 256), 256>>>(x, ph_hi, ph_lo, NN, DD);
    // 2-4: per-layer propagation weight transpose+split
    for (int l = 0; l < NLAYERS; ++l)
        convT_split_k<<<DIVUP(DD * (KP / 4), 256), 256>>>(
            weight + (size_t)l * DD * DD,
            pwt_hi + (size_t)l * DD * KP, pwt_lo + (size_t)l * DD * KP);
    // 5: w_ih split
    conv_split_k<<<DIVUP(TD * (KP / 4), 256), 256>>>(w_ih, pwih_hi, pwih_lo, TD, DD);
    // 6: layer-0 m-GEMM  <-- profiled launch
    mma_gemm_k<false><<<grid1, 256, SMEM_DYN>>>(
        ph_hi, ph_lo, pwt_hi, pwt_lo, nullptr, pm, NN, DD);
    // 7: w_hh split
    conv_split_k<<<DIVUP(TD * (KP / 4), 256), 256>>>(w_hh, pwhh_hi, pwhh_lo, TD, DD);
    // 8-11: CSR build (needed before first scatter)
    zero_deg_k<<<DIVUP(NN, 256), 256>>>(pdeg);
    hist_k<<<DIVUP(EE, 256), 256>>>(dst, pdeg);
    scan_k<<<1, 1024>>>(pdeg, poff, pcur);
    fill_k<<<DIVUP(EE, 256), 256>>>(dst, pcur, peid);

    for (int l = 0; l < NLAYERS; ++l) {
        const float* hin = (l == 0) ? x : ph;

        // m = h @ W[l]  (layer 0 already done in prologue)
        if (l > 0)
            mma_gemm_k<false><<<grid1, 256, SMEM_DYN>>>(
                ph_hi, ph_lo,
                pwt_hi + (size_t)l * DD * KP, pwt_lo + (size_t)l * DD * KP,
                nullptr, pm, NN, DD);

        // agg = scatter_add(m[src] * ew, dst)  -> bf16 split directly
        scatter_csr_k<<<NN, 256>>>(pm, src, ew, poff, peid, pa_hi, pa_lo);

        // gi = agg @ w_ih^T + b_ih ; gh = h @ w_hh^T + b_hh
        mma_gemm_k<true><<<grid3, 256, SMEM_DYN>>>(
            pa_hi, pa_lo, pwih_hi, pwih_lo, b_ih, pgi, NN, TD);
        mma_gemm_k<true><<<grid3, 256, SMEM_DYN>>>(
            ph_hi, ph_lo, pwhh_hi, pwhh_lo, b_hh, pgh, NN, TD);

        // h = GRU(gi, gh, h), fused with split for next layer's GEMMs
        gru_split_k<<<ew_blocks, 256>>>((const float4*)pgi, (const float4*)pgh,
                                        (const float4*)hin, (float4*)ph,
                                        ph_hi, ph_lo);
    }

    // out = relu(h) @ fc_w^T + fc_b
    fc_k<<<DIVUP(NN, 8), 256>>>(ph, fc_w, fc_b, out);
}

// round 17
// speedup vs baseline: 2.9357x; 1.0352x over previous
#include <cuda_runtime.h>
#include <cuda_bf16.h>
#include <math.h>
#include <stdint.h>

// Problem constants (fixed by the reference)
#define NN 20000          // nodes
#define EE 160000         // edges
#define DD 1000           // feature dim
#define TD 3000           // 3*D
#define NLAYERS 3
#define D4 250            // D/4
#define KP 1024           // K padded to multiple of 64
#define KP8 (KP/8)        // uint4 (8 bf16) per padded row = 128
#define NCHUNK2 (KP/32)   // 32 chunks of K=32

#define DIVUP(a,b) (((a)+(b)-1)/(b))

// ---------------- scratch (device globals: sanctioned no-alloc path) --------
__device__ float g_m  [(size_t)NN * DD];   // 80 MB
__device__ float g_gi [(size_t)NN * TD];   // 240 MB
__device__ float g_gh [(size_t)NN * TD];   // 240 MB
__device__ float g_h  [(size_t)NN * DD];   // 80 MB
// bf16 hi/lo split operand buffers (K padded to KP; pad cols stay zero from
// static zero-initialization — kernels only ever write cols [0, DD))
__device__ __nv_bfloat16 g_a_hi [(size_t)NN * KP];
__device__ __nv_bfloat16 g_a_lo [(size_t)NN * KP];
__device__ __nv_bfloat16 g_h_hi [(size_t)NN * KP];
__device__ __nv_bfloat16 g_h_lo [(size_t)NN * KP];
__device__ __nv_bfloat16 g_wih_hi[(size_t)TD * KP];
__device__ __nv_bfloat16 g_wih_lo[(size_t)TD * KP];
__device__ __nv_bfloat16 g_whh_hi[(size_t)TD * KP];
__device__ __nv_bfloat16 g_whh_lo[(size_t)TD * KP];
__device__ __nv_bfloat16 g_wt_hi [(size_t)NLAYERS * DD * KP];
__device__ __nv_bfloat16 g_wt_lo [(size_t)NLAYERS * DD * KP];
// CSR of edge list keyed by dst (rebuilt every launch; deterministic inputs)
__device__ int   g_deg[NN];
__device__ int   g_off[NN + 1];
__device__ int   g_cur[NN];
__device__ int   g_src_s[EE];    // CSR-sorted edge sources
__device__ float g_ew_s [EE];    // CSR-sorted edge weights

// ====================== helpers (sm_80-baseline PTX only) ===================
__device__ __forceinline__ uint32_t smem_u32(const void* p) {
    uint32_t a;
    asm("{ .reg .u64 t; cvta.to.shared.u64 t, %1; cvt.u32.u64 %0, t; }"
        : "=r"(a) : "l"(p));
    return a;
}
__device__ __forceinline__ void cp16(uint32_t s, const void* g, uint32_t sz) {
    asm volatile("cp.async.cg.shared.global [%0], [%1], 16, %2;"
                 :: "r"(s), "l"(g), "r"(sz) : "memory");
}
#define CP_COMMIT() asm volatile("cp.async.commit_group;" ::: "memory")
#define CP_WAIT1()  asm volatile("cp.async.wait_group 1;" ::: "memory")
#define CP_WAIT0()  asm volatile("cp.async.wait_group 0;" ::: "memory")

// D += A(16x16 bf16, row) @ B(16x8 bf16, col)
__device__ __forceinline__ void mma16816(float* d, const uint32_t* a, const uint32_t* b) {
    asm volatile(
        "mma.sync.aligned.m16n8k16.row.col.f32.bf16.bf16.f32 "
        "{%0,%1,%2,%3}, {%4,%5,%6,%7}, {%8,%9}, {%0,%1,%2,%3};"
        : "+f"(d[0]), "+f"(d[1]), "+f"(d[2]), "+f"(d[3])
        : "r"(a[0]), "r"(a[1]), "r"(a[2]), "r"(a[3]), "r"(b[0]), "r"(b[1]));
}
// ldmatrix x4: four 8x8 b16 tiles, one address per lane
__device__ __forceinline__ void ldsm4(uint32_t* r, uint32_t addr) {
    asm volatile("ldmatrix.sync.aligned.m8n8.x4.shared.b16 {%0,%1,%2,%3}, [%4];"
        : "=r"(r[0]), "=r"(r[1]), "=r"(r[2]), "=r"(r[3]) : "r"(addr));
}

__device__ __forceinline__ uint2 split_pack4(float4 v, uint2* lo_out) {
    __nv_bfloat16 h0 = __float2bfloat16(v.x), h1 = __float2bfloat16(v.y);
    __nv_bfloat16 h2 = __float2bfloat16(v.z), h3 = __float2bfloat16(v.w);
    __nv_bfloat16 l0 = __float2bfloat16(v.x - __bfloat162float(h0));
    __nv_bfloat16 l1 = __float2bfloat16(v.y - __bfloat162float(h1));
    __nv_bfloat16 l2 = __float2bfloat16(v.z - __bfloat162float(h2));
    __nv_bfloat16 l3 = __float2bfloat16(v.w - __bfloat162float(h3));
    uint2 ph, pl;
    ph.x = ((uint32_t)__bfloat16_as_ushort(h1) << 16) | __bfloat16_as_ushort(h0);
    ph.y = ((uint32_t)__bfloat16_as_ushort(h3) << 16) | __bfloat16_as_ushort(h2);
    pl.x = ((uint32_t)__bfloat16_as_ushort(l1) << 16) | __bfloat16_as_ushort(l0);
    pl.y = ((uint32_t)__bfloat16_as_ushort(l3) << 16) | __bfloat16_as_ushort(l2);
    *lo_out = pl;
    return ph;
}

// ============================================================================
// fp32 -> bf16 hi/lo split, row-major [M][Kin] -> [M][KP] (tail zero)
// ============================================================================
__global__ __launch_bounds__(256)
void conv_split_k(const float* __restrict__ in, __nv_bfloat16* __restrict__ hi,
                  __nv_bfloat16* __restrict__ lo, int M, int Kin)
{
    int idx = blockIdx.x * blockDim.x + threadIdx.x;   // over M * KP/4
    if (idx >= M * (KP / 4)) return;
    int r  = idx / (KP / 4);
    int c  = (idx - r * (KP / 4)) * 4;
    float4 v = make_float4(0.f, 0.f, 0.f, 0.f);
    if (c + 3 < Kin) v = *(const float4*)(in + (size_t)r * Kin + c);
    uint2 pl;
    uint2 ph = split_pack4(v, &pl);
    *(uint2*)(hi + (size_t)r * KP + c) = ph;
    *(uint2*)(lo + (size_t)r * KP + c) = pl;
}

// ============================================================================
// weight[l] is [K=1000][N=1000] (N contiguous); emit transposed split
// ============================================================================
__global__ __launch_bounds__(256)
void convT_split_k(const float* __restrict__ w, __nv_bfloat16* __restrict__ hi,
                   __nv_bfloat16* __restrict__ lo)
{
    int idx = blockIdx.x * blockDim.x + threadIdx.x;   // over DD * KP/4
    if (idx >= DD * (KP / 4)) return;
    int n = idx / (KP / 4);
    int k = (idx - n * (KP / 4)) * 4;
    float4 v = make_float4(0.f, 0.f, 0.f, 0.f);
    if (k + 3 < DD) {
        v.x = w[(size_t)(k    ) * DD + n];
        v.y = w[(size_t)(k + 1) * DD + n];
        v.z = w[(size_t)(k + 2) * DD + n];
        v.w = w[(size_t)(k + 3) * DD + n];
    }
    uint2 pl;
    uint2 ph = split_pack4(v, &pl);
    *(uint2*)(hi + (size_t)n * KP + k) = ph;
    *(uint2*)(lo + (size_t)n * KP + k) = pl;
}

// ============================================================================
// CSR build (per launch; deterministic edge list)
// ============================================================================
__global__ void zero_deg_k(int* __restrict__ deg)
{
    int i = blockIdx.x * blockDim.x + threadIdx.x;
    if (i < NN) deg[i] = 0;
}
__global__ void hist_k(const int* __restrict__ dst, int* __restrict__ deg)
{
    int e = blockIdx.x * blockDim.x + threadIdx.x;
    if (e < EE) atomicAdd(&deg[dst[e]], 1);
}
__global__ __launch_bounds__(1024)
void scan_k(const int* __restrict__ deg, int* __restrict__ off,
            int* __restrict__ cur)
{
    __shared__ int part[1024];
    const int tid = threadIdx.x;
    const int per = DIVUP(NN, 1024);     // 20
    const int base = tid * per;
    int loc[DIVUP(NN, 1024)];
    int s = 0;
#pragma unroll
    for (int i = 0; i < per; ++i) {
        int idx = base + i;
        int v = (idx < NN) ? deg[idx] : 0;
        loc[i] = v;
        s += v;
    }
    part[tid] = s;
    __syncthreads();
    for (int d = 1; d < 1024; d <<= 1) {
        int v = (tid >= d) ? part[tid - d] : 0;
        __syncthreads();
        part[tid] += v;
        __syncthreads();
    }
    int run = part[tid] - s;
#pragma unroll
    for (int i = 0; i < per; ++i) {
        int idx = base + i;
        if (idx < NN) { off[idx] = run; cur[idx] = run; run += loc[i]; }
    }
    if (tid == 1023) off[NN] = run;
}
// fill CSR-sorted src/weight directly (removes eid indirection in scatter)
__global__ void fill_k(const int* __restrict__ src, const int* __restrict__ dst,
                       const float* __restrict__ ew, int* __restrict__ cur,
                       int* __restrict__ src_s, float* __restrict__ ew_s)
{
    int e = blockIdx.x * blockDim.x + threadIdx.x;
    if (e < EE) {
        int p = atomicAdd(&cur[dst[e]], 1);
        src_s[p] = src[e];
        ew_s[p]  = ew[e];
    }
}

// ============================================================================
// CSR scatter: block per dst node; emits bf16 hi/lo split of agg directly
// ============================================================================
__global__ __launch_bounds__(256)
void scatter_csr_k(const float* __restrict__ m, const int* __restrict__ off,
                   const int* __restrict__ src_s, const float* __restrict__ ew_s,
                   __nv_bfloat16* __restrict__ ahi, __nv_bfloat16* __restrict__ alo)
{
    const int n = blockIdx.x;
    const int t = threadIdx.x;
    if (t >= D4) return;
    const int s0 = off[n];
    const int s1 = off[n + 1];
    float4 acc = make_float4(0.f, 0.f, 0.f, 0.f);
    for (int i = s0; i < s1; ++i) {
        const int s = src_s[i];
        const float w = ew_s[i];
        const float4 v = *(const float4*)(m + (size_t)s * DD + t * 4);
        acc.x += v.x * w;
        acc.y += v.y * w;
        acc.z += v.z * w;
        acc.w += v.w * w;
    }
    uint2 pl;
    uint2 ph = split_pack4(acc, &pl);
    *(uint2*)(ahi + (size_t)n * KP + t * 4) = ph;
    *(uint2*)(alo + (size_t)n * KP + t * 4) = pl;
}

// ============================================================================
// Shared GEMM core: C[M,Nn] = Ahi@Bhi^T + Ahi@Blo^T + Alo@Bhi^T (+ bias)
// CTA tile 128x128, K chunk 32, 2-stage cp.async, 2 CTAs/SM, ldmatrix.x4.
// ============================================================================
#define ASTRIDE 80
#define TILE_SB (128 * ASTRIDE)   // 10240 B
#define STAGE_SB (4 * TILE_SB)    // 40960 B
#define SMEM_DYN (2 * STAGE_SB)   // 81920 B

template<bool BIAS>
__device__ __forceinline__
void gemm_core(const __nv_bfloat16* __restrict__ Ahi, const __nv_bfloat16* __restrict__ Alo,
               const __nv_bfloat16* __restrict__ Bhi, const __nv_bfloat16* __restrict__ Blo,
               const float* __restrict__ bias, float* __restrict__ C,
               int M, int Nn, int col0, char* smem)
{
    const int tid  = threadIdx.x;
    const int lane = tid & 31;
    const int wid  = tid >> 5;
    const int gr   = lane >> 2;
    const int gc   = lane & 3;
    const int wm   = wid >> 2;      // 0..1 (64-row half)
    const int wn   = wid & 3;       // 0..3 (32-col quarter)
    const int row0 = blockIdx.y * 128;

    const uint4* pAhi = (const uint4*)Ahi;
    const uint4* pAlo = (const uint4*)Alo;
    const uint4* pBhi = (const uint4*)Bhi;
    const uint4* pBlo = (const uint4*)Blo;

    const uint32_t sbase = smem_u32(smem);

    float acc[4][4][4];
#pragma unroll
    for (int i = 0; i < 4; i++)
#pragma unroll
        for (int j = 0; j < 4; j++)
#pragma unroll
            for (int k = 0; k < 4; k++) acc[i][j][k] = 0.f;

    // ldmatrix per-lane base offsets within a tile
    const int g8 = lane >> 3;       // matrix index 0..3
    const int r8 = lane & 7;        // row within 8x8
    const uint32_t aoff = (uint32_t)((wm * 64 + (g8 & 1) * 8 + r8) * ASTRIDE
                                     + (g8 >> 1) * 16);
    const uint32_t boff = (uint32_t)((wn * 32 + (g8 >> 1) * 8 + r8) * ASTRIDE
                                     + (g8 & 1) * 16);

    auto load_chunk = [&](int c, int stage) {
        const uint32_t st = sbase + stage * STAGE_SB;
        const int k0u = c * 4;
#pragma unroll
        for (int half = 0; half < 2; ++half) {
            const int s = tid + half * 256;
            const int row = s >> 2;
            const int u = s & 3;
            const uint32_t soff = (uint32_t)(row * ASTRIDE + u * 16);
            const int ar = row0 + row;
            const uint32_t asz = (ar < M) ? 16u : 0u;
            const size_t ga = (size_t)((ar < M) ? ar : 0) * KP8 + (k0u + u);
            cp16(st + 0 * TILE_SB + soff, pAhi + ga, asz);
            cp16(st + 1 * TILE_SB + soff, pAlo + ga, asz);
            const int br = col0 + row;
            const uint32_t bsz = (br < Nn) ? 16u : 0u;
            const size_t gb = (size_t)((br < Nn) ? br : 0) * KP8 + (k0u + u);
            cp16(st + 2 * TILE_SB + soff, pBhi + gb, bsz);
            cp16(st + 3 * TILE_SB + soff, pBlo + gb, bsz);
        }
        CP_COMMIT();
    };

    load_chunk(0, 0);

    for (int c = 0; c < NCHUNK2; ++c) {
        if (c + 1 < NCHUNK2) {
            load_chunk(c + 1, (c + 1) & 1);
            CP_WAIT1();
        } else {
            CP_WAIT0();
        }
        __syncthreads();

        const uint32_t st = sbase + (c & 1) * STAGE_SB;
        const uint32_t sAh = st + 0 * TILE_SB + aoff;
        const uint32_t sAl = st + 1 * TILE_SB + aoff;
        const uint32_t sBh = st + 2 * TILE_SB + boff;
        const uint32_t sBl = st + 3 * TILE_SB + boff;

#pragma unroll
        for (int ks = 0; ks < 2; ++ks) {
            const uint32_t ko = ks * 32;
            uint32_t a[4][4];
            uint32_t b[2][8];

            ldsm4(b[0] + 0, sBh + ko);
            ldsm4(b[0] + 4, sBh + ko + 16 * ASTRIDE);
            ldsm4(b[1] + 0, sBl + ko);
            ldsm4(b[1] + 4, sBl + ko + 16 * ASTRIDE);
#pragma unroll
            for (int mt = 0; mt < 4; ++mt)
                ldsm4(a[mt], sAh + ko + mt * 16 * ASTRIDE);
            // hi*hi
#pragma unroll
            for (int mt = 0; mt < 4; ++mt)
#pragma unroll
                for (int nt = 0; nt < 4; ++nt)
                    mma16816(acc[mt][nt], a[mt], b[0] + (nt >> 1) * 4 + (nt & 1) * 2);
            // hi*lo
#pragma unroll
            for (int mt = 0; mt < 4; ++mt)
#pragma unroll
                for (int nt = 0; nt < 4; ++nt)
                    mma16816(acc[mt][nt], a[mt], b[1] + (nt >> 1) * 4 + (nt & 1) * 2);
            // a_lo
#pragma unroll
            for (int mt = 0; mt < 4; ++mt)
                ldsm4(a[mt], sAl + ko + mt * 16 * ASTRIDE);
            // lo*hi
#pragma unroll
            for (int mt = 0; mt < 4; ++mt)
#pragma unroll
                for (int nt = 0; nt < 4; ++nt)
                    mma16816(acc[mt][nt], a[mt], b[0] + (nt >> 1) * 4 + (nt & 1) * 2);
        }
        __syncthreads();
    }

    // epilogue
#pragma unroll
    for (int mt = 0; mt < 4; ++mt) {
        const int r1 = row0 + wm * 64 + mt * 16 + gr;
        const int r2 = r1 + 8;
#pragma unroll
        for (int nt = 0; nt < 4; ++nt) {
            const int cc = col0 + wn * 32 + nt * 8 + 2 * gc;
            if (cc < Nn) {
                float bx = 0.f, by = 0.f;
                if (BIAS) { bx = bias[cc]; by = bias[cc + 1]; }
                if (r1 < M) {
                    float2 v = make_float2(acc[mt][nt][0] + bx, acc[mt][nt][1] + by);
                    *(float2*)&C[(size_t)r1 * Nn + cc] = v;
                }
                if (r2 < M) {
                    float2 v = make_float2(acc[mt][nt][2] + bx, acc[mt][nt][3] + by);
                    *(float2*)&C[(size_t)r2 * Nn + cc] = v;
                }
            }
        }
    }
}

// standalone GEMM (gi): C = A @ B^T + bias
__global__ __launch_bounds__(256, 2)
void mma_gemm_k(const __nv_bfloat16* __restrict__ Ahi, const __nv_bfloat16* __restrict__ Alo,
                const __nv_bfloat16* __restrict__ Bhi, const __nv_bfloat16* __restrict__ Blo,
                const float* __restrict__ bias, float* __restrict__ C,
                int M, int Nn)
{
    extern __shared__ char smem[];
    gemm_core<true>(Ahi, Alo, Bhi, Blo, bias, C, M, Nn, blockIdx.x * 128, smem);
}

// fused m + gh GEMM: shared A (h split).
//   blockIdx.x <  8 : C_m[., 0..1000)  = A @ Wt^T          (no bias)
//   blockIdx.x >= 8 : C_gh[., 0..3000) = A @ w_hh^T + b_hh
__global__ __launch_bounds__(256, 2)
void mma_gemm_mgh_k(const __nv_bfloat16* __restrict__ Ahi, const __nv_bfloat16* __restrict__ Alo,
                    const __nv_bfloat16* __restrict__ Bwt_hi, const __nv_bfloat16* __restrict__ Bwt_lo,
                    const __nv_bfloat16* __restrict__ Bwhh_hi, const __nv_bfloat16* __restrict__ Bwhh_lo,
                    const float* __restrict__ b_hh,
                    float* __restrict__ Cm, float* __restrict__ Cgh, int M)
{
    extern __shared__ char smem[];
    if (blockIdx.x < 8) {
        gemm_core<false>(Ahi, Alo, Bwt_hi, Bwt_lo, nullptr, Cm,
                         M, DD, blockIdx.x * 128, smem);
    } else {
        gemm_core<true>(Ahi, Alo, Bwhh_hi, Bwhh_lo, b_hh, Cgh,
                        M, TD, (blockIdx.x - 8) * 128, smem);
    }
}

// ============================================================================
// GRU elementwise, fused with bf16 hi/lo split of the new h
// ============================================================================
__device__ __forceinline__ float gru1(float ir, float iz, float inn,
                                      float hr, float hz, float hn, float h)
{
    float r = 1.f / (1.f + expf(-(ir + hr)));
    float z = 1.f / (1.f + expf(-(iz + hz)));
    float n = tanhf(inn + r * hn);
    return (1.f - z) * n + z * h;
}

__global__ __launch_bounds__(256)
void gru_split_k(const float4* __restrict__ gi, const float4* __restrict__ gh,
                 const float4* __restrict__ hin, float4* __restrict__ hout,
                 __nv_bfloat16* __restrict__ hhi, __nv_bfloat16* __restrict__ hlo)
{
    int idx = blockIdx.x * blockDim.x + threadIdx.x;
    if (idx >= NN * D4) return;
    int n  = idx / D4;
    int dv = idx - n * D4;
    size_t b3 = (size_t)n * (3 * D4);
    float4 ir = gi[b3 + dv];
    float4 iz = gi[b3 + D4 + dv];
    float4 in_ = gi[b3 + 2 * D4 + dv];
    float4 hr = gh[b3 + dv];
    float4 hz = gh[b3 + D4 + dv];
    float4 hn = gh[b3 + 2 * D4 + dv];
    float4 h = hin[(size_t)n * D4 + dv];
    float4 o;
    o.x = gru1(ir.x, iz.x, in_.x, hr.x, hz.x, hn.x, h.x);
    o.y = gru1(ir.y, iz.y, in_.y, hr.y, hz.y, hn.y, h.y);
    o.z = gru1(ir.z, iz.z, in_.z, hr.z, hz.z, hn.z, h.z);
    o.w = gru1(ir.w, iz.w, in_.w, hr.w, hz.w, hn.w, h.w);
    hout[(size_t)n * D4 + dv] = o;
    uint2 pl;
    uint2 ph = split_pack4(o, &pl);
    *(uint2*)(hhi + (size_t)n * KP + dv * 4) = ph;
    *(uint2*)(hlo + (size_t)n * KP + dv * 4) = pl;
}

// ============================================================================
// Final: out[n] = sum_d relu(h[n,d]) * fc_w[d] + fc_b   (warp per node)
// ============================================================================
__global__ __launch_bounds__(256)
void fc_k(const float* __restrict__ h, const float* __restrict__ fw,
          const float* __restrict__ fb, float* __restrict__ out)
{
    int warp = (blockIdx.x * 256 + threadIdx.x) >> 5;
    int lane = threadIdx.x & 31;
    if (warp >= NN) return;
    const float4* h4 = (const float4*)(h + (size_t)warp * DD);
    const float4* w4 = (const float4*)fw;
    float s = 0.f;
    for (int i = lane; i < D4; i += 32) {
        float4 hv = h4[i];
        float4 wv = w4[i];
        s += fmaxf(hv.x, 0.f) * wv.x + fmaxf(hv.y, 0.f) * wv.y +
             fmaxf(hv.z, 0.f) * wv.z + fmaxf(hv.w, 0.f) * wv.w;
    }
#pragma unroll
    for (int off = 16; off; off >>= 1)
        s += __shfl_down_sync(0xffffffffu, s, off);
    if (lane == 0) out[warp] = s + fb[0];
}

// ============================================================================
// launch
// ============================================================================
extern "C" void kernel_launch(void* const* d_in, const int* in_sizes, int n_in,
                              void* d_out, int out_size)
{
    const float* x      = (const float*)d_in[0];
    const int*   ei     = (const int*)  d_in[1];
    const float* ew     = (const float*)d_in[2];
    const float* weight = (const float*)d_in[3];
    const float* w_ih   = (const float*)d_in[4];
    const float* w_hh   = (const float*)d_in[5];
    const float* b_ih   = (const float*)d_in[6];
    const float* b_hh   = (const float*)d_in[7];
    const float* fc_w   = (const float*)d_in[8];
    const float* fc_b   = (const float*)d_in[9];
    float* out = (float*)d_out;

    float *pm, *pgi, *pgh, *ph;
    __nv_bfloat16 *pa_hi, *pa_lo, *ph_hi, *ph_lo;
    __nv_bfloat16 *pwih_hi, *pwih_lo, *pwhh_hi, *pwhh_lo, *pwt_hi, *pwt_lo;
    int *pdeg, *poff, *pcur, *psrc_s;
    float *pew_s;
    cudaGetSymbolAddress((void**)&pm,     g_m);
    cudaGetSymbolAddress((void**)&pgi,    g_gi);
    cudaGetSymbolAddress((void**)&pgh,    g_gh);
    cudaGetSymbolAddress((void**)&ph,     g_h);
    cudaGetSymbolAddress((void**)&pa_hi,  g_a_hi);
    cudaGetSymbolAddress((void**)&pa_lo,  g_a_lo);
    cudaGetSymbolAddress((void**)&ph_hi,  g_h_hi);
    cudaGetSymbolAddress((void**)&ph_lo,  g_h_lo);
    cudaGetSymbolAddress((void**)&pwih_hi, g_wih_hi);
    cudaGetSymbolAddress((void**)&pwih_lo, g_wih_lo);
    cudaGetSymbolAddress((void**)&pwhh_hi, g_whh_hi);
    cudaGetSymbolAddress((void**)&pwhh_lo, g_whh_lo);
    cudaGetSymbolAddress((void**)&pwt_hi,  g_wt_hi);
    cudaGetSymbolAddress((void**)&pwt_lo,  g_wt_lo);
    cudaGetSymbolAddress((void**)&pdeg,   g_deg);
    cudaGetSymbolAddress((void**)&poff,   g_off);
    cudaGetSymbolAddress((void**)&pcur,   g_cur);
    cudaGetSymbolAddress((void**)&psrc_s, g_src_s);
    cudaGetSymbolAddress((void**)&pew_s,  g_ew_s);

    const int* src = ei;
    const int* dst = ei + EE;

    cudaFuncSetAttribute(mma_gemm_k,
                         cudaFuncAttributeMaxDynamicSharedMemorySize, SMEM_DYN);
    cudaFuncSetAttribute(mma_gemm_mgh_k,
                         cudaFuncAttributeMaxDynamicSharedMemorySize, SMEM_DYN);

    dim3 grid_mgh(8 + DIVUP(TD, 128), DIVUP(NN, 128));  // 32 x 157
    dim3 grid3(DIVUP(TD, 128), DIVUP(NN, 128));         // 24 x 157
    const int ew_blocks = DIVUP(NN * D4, 256);

    // ---- prologue: conversions + CSR build ----
    conv_split_k<<<DIVUP(NN * (KP / 4), 256), 256>>>(x, ph_hi, ph_lo, NN, DD);
    for (int l = 0; l < NLAYERS; ++l)
        convT_split_k<<<DIVUP(DD * (KP / 4), 256), 256>>>(
            weight + (size_t)l * DD * DD,
            pwt_hi + (size_t)l * DD * KP, pwt_lo + (size_t)l * DD * KP);
    conv_split_k<<<DIVUP(TD * (KP / 4), 256), 256>>>(w_ih, pwih_hi, pwih_lo, TD, DD);
    conv_split_k<<<DIVUP(TD * (KP / 4), 256), 256>>>(w_hh, pwhh_hi, pwhh_lo, TD, DD);
    zero_deg_k<<<DIVUP(NN, 256), 256>>>(pdeg);
    hist_k<<<DIVUP(EE, 256), 256>>>(dst, pdeg);
    scan_k<<<1, 1024>>>(pdeg, poff, pcur);
    fill_k<<<DIVUP(EE, 256), 256>>>(src, dst, ew, pcur, psrc_s, pew_s);

    for (int l = 0; l < NLAYERS; ++l) {
        const float* hin = (l == 0) ? x : ph;

        // fused: m = h @ W[l] ; gh = h @ w_hh^T + b_hh  (shared A operand)
        mma_gemm_mgh_k<<<grid_mgh, 256, SMEM_DYN>>>(
            ph_hi, ph_lo,
            pwt_hi + (size_t)l * DD * KP, pwt_lo + (size_t)l * DD * KP,
            pwhh_hi, pwhh_lo, b_hh, pm, pgh, NN);

        // agg = scatter_add(m[src] * ew, dst)  -> bf16 split directly
        scatter_csr_k<<<NN, 256>>>(pm, poff, psrc_s, pew_s, pa_hi, pa_lo);

        // gi = agg @ w_ih^T + b_ih
        mma_gemm_k<<<grid3, 256, SMEM_DYN>>>(
            pa_hi, pa_lo, pwih_hi, pwih_lo, b_ih, pgi, NN, TD);

        // h = GRU(gi, gh, h), fused with split for next layer's GEMMs
        gru_split_k<<<ew_blocks, 256>>>((const float4*)pgi, (const float4*)pgh,
                                        (const float4*)hin, (float4*)ph,
                                        ph_hi, ph_lo);
    }

    // out = relu(h) @ fc_w^T + fc_b
    fc_k<<<DIVUP(NN, 8), 256>>>(ph, fc_w, fc_b, out);
}